// round 12
// baseline (speedup 1.0000x reference)
#include <cuda_runtime.h>
#include <math.h>

#define HH 512
#define WW 512
#define NB 32
#define MS 10
#define SH 21            // 2*MS+1
#define NS 441           // SH*SH
#define NPIX (HH*WW)     // 262144
#define KAREA (492.0*492.0)
#define EPS 1e-8

#define TBAND 14                 // image rows per band
#define NBAND 37                 // 37*14 = 518 >= 512
#define TROWS 34                 // TBAND + 20
#define TCOLS 532
#define ISTR 516
#define CTH 294                  // 21 p-values x 14 rows
#define NLD ((TBAND*128 + CTH - 1) / CTH)          // 7 float4 loads/thread
#define SMEM_CORR ((TROWS*TCOLS + TBAND*ISTR) * 4) // 101248
#define SMEM_SP (40*512*4)

// ---------------- scratch ----------------
__device__ double g_tstats[2];
__device__ double g_colP1[NB*8*WW];        // per-slab column sums
__device__ double g_colP2[NB*8*WW];
__device__ float  g_cc[NB*NS];             // accumulated correlations
__device__ float  g_shift[NB*2];

// ---------------- K1: per-slab column sums + template stats + zero g_cc ----------------
__global__ void __launch_bounds__(512) k_colpart(const float* __restrict__ fr,
                                                 const float* __restrict__ tp) {
    int b = blockIdx.x;          // 0..NB ; b==NB -> template/zero duty
    int slab = blockIdx.y;       // 0..7
    int x = threadIdx.x;         // 512
    if (b == NB) {
        // zero 1/8 of g_cc
        int base = slab * (NB * NS / 8);
        for (int i = x; i < NB * NS / 8; i += 512) g_cc[base + i] = 0.f;
        if (slab != 0) return;
        // template stats (slab 0 only), direct write
        __shared__ double r1[512], r2[512];
        double c1 = 0.0, c2d = 0.0;
        for (int s = 0; s < 8; ++s) {
            float a1 = 0.f, a2 = 0.f, b1 = 0.f, b2 = 0.f;
#pragma unroll 4
            for (int y = s * 64; y < s * 64 + 64; y += 2) {
                float v0 = tp[y * WW + x];
                float v1 = tp[(y + 1) * WW + x];
                a1 += v0; b1 += v1;
                a2 = fmaf(v0, v0, a2); b2 = fmaf(v1, v1, b2);
            }
            c1  += (double)a1 + (double)b1;
            c2d += (double)a2 + (double)b2;
        }
        r1[x] = c1; r2[x] = c2d;
        __syncthreads();
        for (int st = 256; st > 0; st >>= 1) {
            if (x < st) { r1[x] += r1[x + st]; r2[x] += r2[x + st]; }
            __syncthreads();
        }
        if (x == 0) { g_tstats[0] = r1[0]; g_tstats[1] = r2[0]; }
        return;
    }
    const float* src = fr + (size_t)b * NPIX;
    int y0 = slab * 64;
    float s1a = 0.f, s1b = 0.f, s2a = 0.f, s2b = 0.f;
#pragma unroll 4
    for (int y = y0; y < y0 + 64; y += 2) {
        float v0 = src[y * WW + x];
        float v1 = src[(y + 1) * WW + x];
        s1a += v0; s1b += v1;
        s2a = fmaf(v0, v0, s2a); s2b = fmaf(v1, v1, s2b);
    }
    g_colP1[((size_t)b * 8 + slab) * WW + x] = (double)s1a + (double)s1b;
    g_colP2[((size_t)b * 8 + slab) * WW + x] = (double)s2a + (double)s2b;
}

// ---------------- K2: the correlation (hot kernel) ----------------
template<int SLOT>
__device__ __forceinline__ float wslot(const float4* w) {
    return ((SLOT & 3) == 0) ? w[(SLOT % 24) >> 2].x
         : ((SLOT & 3) == 1) ? w[(SLOT % 24) >> 2].y
         : ((SLOT & 3) == 2) ? w[(SLOT % 24) >> 2].z
                             : w[(SLOT % 24) >> 2].w;
}

template<int X, int J> struct FmaJ {
    static __device__ __forceinline__ void run(float v, const float4* w, float* acc) {
        acc[J] = fmaf(v, wslot<(X + 20 - J) % 24>(w), acc[J]);
        FmaJ<X, J + 1>::run(v, w, acc);
    }
};
template<int X> struct FmaJ<X, SH> {
    static __device__ __forceinline__ void run(float, const float4*, float*) {}
};

template<int SG, int NSG, bool LAST> struct Step {
    static __device__ __forceinline__ void run(const float* __restrict__ tr,
                                               const float* __restrict__ ir,
                                               float4* w, float4* iv, float* acc) {
        iv[(SG + 1) & 1] = *(const float4*)(ir + 4 * SG + 4);
        FmaJ<4 * SG + 0, 0>::run(iv[SG & 1].x, w, acc);
        FmaJ<4 * SG + 1, 0>::run(iv[SG & 1].y, w, acc);
        FmaJ<4 * SG + 2, 0>::run(iv[SG & 1].z, w, acc);
        FmaJ<4 * SG + 3, 0>::run(iv[SG & 1].w, w, acc);
        if (!LAST)
            w[SG] = *(const float4*)(tr + 4 * SG + 24);   // refill dead quad
        Step<SG + 1, NSG, LAST>::run(tr, ir, w, iv, acc);
    }
};
template<int NSG, bool LAST> struct Step<NSG, NSG, LAST> {
    static __device__ __forceinline__ void run(const float*, const float*,
                                               float4*, float4*, float*) {}
};

__device__ __forceinline__ void pf_load(float4* pf, const float* __restrict__ im,
                                        int y0, int tid) {
#pragma unroll
    for (int k = 0; k < NLD; ++k) {
        int idx = tid + k * CTH;
        float4 v = make_float4(0.f, 0.f, 0.f, 0.f);
        if (idx < TBAND * 128) {
            int r = idx >> 7, c4 = idx & 127;
            if (y0 + r < HH) v = *(const float4*)(im + r * WW + 4 * c4);
        }
        pf[k] = v;
    }
}

__global__ void __launch_bounds__(CTH, 2)
k_corr(const float* __restrict__ fr, const float* __restrict__ tp) {
    int band = blockIdx.x;                  // 0..36
    int fg   = blockIdx.y;                  // 0..7 (4 frames each)
    int y0 = band * TBAND;
    extern __shared__ float sm[];
    float* sm_t = sm;                       // TROWS x TCOLS
    float* sm_i = sm + TROWS * TCOLS;       // TBAND x ISTR
    int tid = threadIdx.x;

    // template tile once per block; wrapped rows/cols
    for (int idx = tid; idx < TROWS * 256; idx += CTH) {
        int r = idx >> 8, c2 = idx & 255;
        int gy = (y0 - MS + r) & (HH - 1);
        float2 v = *(const float2*)(tp + gy * WW + 2 * c2);
        *(float2*)(sm_t + r * TCOLS + 10 + 2 * c2) = v;
    }
    for (int idx = tid; idx < TROWS * 20; idx += CTH) {
        int r = idx / 20, e = idx - r * 20;
        int c = (e < 10) ? e : (e + 512);
        int gy = (y0 - MS + r) & (HH - 1);
        int gx = (c - 10) & (WW - 1);
        sm_t[r * TCOLS + c] = tp[gy * WW + gx];
    }

    int yl = tid % TBAND;
    int p  = tid / TBAND;
    const float* trow0 = sm_t + (yl + 2 * MS - p) * TCOLS;
    const float* irow0 = sm_i + yl * ISTR;
    int b0 = fg * 4;

    float4 pf[NLD];
    pf_load(pf, fr + (size_t)b0 * NPIX + (size_t)y0 * WW, y0, tid);

    for (int f = 0; f < 4; ++f) {
        __syncthreads();                    // sm_i (sred) fully consumed
#pragma unroll
        for (int k = 0; k < NLD; ++k) {     // store prefetched image
            int idx = tid + k * CTH;
            if (idx < TBAND * 128) {
                int r = idx >> 7, c4 = idx & 127;
                *(float4*)(sm_i + r * ISTR + 4 * c4) = pf[k];
            }
        }
        __syncthreads();
        if (f < 3)                          // overlap next frame's DRAM reads
            pf_load(pf, fr + (size_t)(b0 + f + 1) * NPIX + (size_t)y0 * WW, y0, tid);

        float acc[SH];
#pragma unroll
        for (int j = 0; j < SH; ++j) acc[j] = 0.f;
        float4 w[6];
#pragma unroll
        for (int m = 0; m < 6; ++m) w[m] = *(const float4*)(trow0 + 4 * m);
        float4 iv[2];
        iv[0] = *(const float4*)irow0;

        const float* tr = trow0;
        const float* ir = irow0;
#pragma unroll 1
        for (int it = 0; it < 21; ++it) {   // 21 x 24 = 504 px
            Step<0, 6, false>::run(tr, ir, w, iv, acc);
            tr += 24; ir += 24;
        }
        Step<0, 2, true>::run(tr, ir, w, iv, acc);   // px 504..511

        __syncthreads();
        float* sred = sm_i;                 // reuse image buffer
#pragma unroll
        for (int j = 0; j < SH; ++j) sred[(p * SH + j) * TBAND + yl] = acc[j];
        __syncthreads();
        for (int s = tid; s < NS; s += CTH) {
            float v = 0.f;
#pragma unroll
            for (int k = 0; k < TBAND; ++k) v += sred[s * TBAND + k];
            atomicAdd(&g_cc[(size_t)(b0 + f) * NS + s], v);
        }
    }
}

// ---------------- K3: denominators + ncc + argmax + subpixel (fused) ----------------
__global__ void __launch_bounds__(512) k_statspeak(const float* __restrict__ fr) {
    __shared__ double scol1[512], scol2[512];
    __shared__ double srow1[40], srow2[40];
    __shared__ double rowPre1[41], rowPre2[41];
    __shared__ double colPre1[21], colPre2[21];
    __shared__ double colSuf1[21], colSuf2[21];
    __shared__ double spart1[16], spart2[16];
    __shared__ double sS1s, sS2s;
    __shared__ float PP1[41*41], PP2[41*41];
    __shared__ float sden[NS];
    __shared__ float sncc[NS];
    __shared__ float rv[512];
    __shared__ int   ri[512];
    extern __shared__ float sedge[];         // 40*512

    int b = blockIdx.x, tid = threadIdx.x;   // 512 threads
    {
        double c1 = 0.0, c2d = 0.0;
#pragma unroll
        for (int s = 0; s < 8; ++s) {
            c1  += g_colP1[((size_t)b * 8 + s) * WW + tid];
            c2d += g_colP2[((size_t)b * 8 + s) * WW + tid];
        }
        scol1[tid] = c1; scol2[tid] = c2d;
    }
    const float* im = fr + (size_t)b * NPIX;
    for (int idx = tid; idx < 40 * 512; idx += 512) {
        int r = idx >> 9, c = idx & 511;
        int y = (r < 20) ? r : (472 + r);
        sedge[idx] = im[y * WW + c];
    }
    __syncthreads();

    int wid = tid >> 5, lane = tid & 31;
    for (int r = wid; r < 40; r += 16) {
        double a = 0.0, c2 = 0.0;
        for (int c = lane; c < 512; c += 32) {
            double v = (double)sedge[r * 512 + c];
            a += v; c2 += v * v;
        }
#pragma unroll
        for (int s = 16; s > 0; s >>= 1) {
            a  += __shfl_down_sync(0xffffffffu, a, s);
            c2 += __shfl_down_sync(0xffffffffu, c2, s);
        }
        if (lane == 0) { srow1[r] = a; srow2[r] = c2; }
    }
    for (int idx = tid; idx < 41 * 41; idx += 512) { PP1[idx] = 0.f; PP2[idx] = 0.f; }
    __syncthreads();

    for (int idx = tid; idx < 1600; idx += 512) {
        int r = idx / 40, cc = idx - r * 40;
        int col = (cc < 20) ? cc : (472 + cc);
        float v = sedge[r * 512 + col];
        PP1[(r + 1) * 41 + cc + 1] = v;
        PP2[(r + 1) * 41 + cc + 1] = v * v;
    }
    {
        double a = scol1[tid], c2 = scol2[tid];
#pragma unroll
        for (int s = 16; s > 0; s >>= 1) {
            a  += __shfl_down_sync(0xffffffffu, a, s);
            c2 += __shfl_down_sync(0xffffffffu, c2, s);
        }
        if (lane == 0) { spart1[wid] = a; spart2[wid] = c2; }
    }
    __syncthreads();

    if (tid < 41) {
        float a = 0.f, c2 = 0.f;
        for (int c = 0; c < 41; ++c) {
            a  += PP1[tid * 41 + c]; PP1[tid * 41 + c] = a;
            c2 += PP2[tid * 41 + c]; PP2[tid * 41 + c] = c2;
        }
    }
    if (tid == 64)  { double a = 0; rowPre1[0] = 0; for (int r = 0; r < 40; ++r) { a += srow1[r]; rowPre1[r+1] = a; } }
    if (tid == 96)  { double a = 0; rowPre2[0] = 0; for (int r = 0; r < 40; ++r) { a += srow2[r]; rowPre2[r+1] = a; } }
    if (tid == 128) { double a = 0; colPre1[0] = 0; for (int c = 0; c < 20; ++c) { a += scol1[c]; colPre1[c+1] = a; } }
    if (tid == 160) { double a = 0; colPre2[0] = 0; for (int c = 0; c < 20; ++c) { a += scol2[c]; colPre2[c+1] = a; } }
    if (tid == 192) { double a = 0; colSuf1[20] = 0; for (int j = 19; j >= 0; --j) { a += scol1[492+j]; colSuf1[j] = a; } }
    if (tid == 224) { double a = 0; colSuf2[20] = 0; for (int j = 19; j >= 0; --j) { a += scol2[492+j]; colSuf2[j] = a; } }
    if (tid == 256) { double a = 0; for (int w = 0; w < 16; ++w) a += spart1[w]; sS1s = a; }
    if (tid == 288) { double a = 0; for (int w = 0; w < 16; ++w) a += spart2[w]; sS2s = a; }
    __syncthreads();

    if (tid < 41) {
        float a = 0.f, c2 = 0.f;
        for (int r = 0; r < 41; ++r) {
            a  += PP1[r * 41 + tid]; PP1[r * 41 + tid] = a;
            c2 += PP2[r * 41 + tid]; PP2[r * 41 + tid] = c2;
        }
    }
    __syncthreads();

#define RECT(PP, r0, r1, c0, c1) \
    (PP[(r1)*41+(c1)] - PP[(r0)*41+(c1)] - PP[(r1)*41+(c0)] + PP[(r0)*41+(c0)])
    if (tid < NS) {
        int p = tid / SH, j = tid - p * SH;
        double rsum1 = rowPre1[p] + (rowPre1[40] - rowPre1[p + 20]);
        double rsum2 = rowPre2[p] + (rowPre2[40] - rowPre2[p + 20]);
        double csum1 = colPre1[j] + colSuf1[j];
        double csum2 = colPre2[j] + colSuf2[j];
        float q1 = RECT(PP1, 0, p, 0, j) + RECT(PP1, 0, p, 20 + j, 40)
                 + RECT(PP1, p + 20, 40, 0, j) + RECT(PP1, p + 20, 40, 20 + j, 40);
        float q2 = RECT(PP2, 0, p, 0, j) + RECT(PP2, 0, p, 20 + j, 40)
                 + RECT(PP2, p + 20, 40, 0, j) + RECT(PP2, p + 20, 40, 20 + j, 40);
        double w1 = sS1s - rsum1 - csum1 + (double)q1;
        double w2 = sS2s - rsum2 - csum2 + (double)q2;
        double m1 = w1 / KAREA;
        double m2 = w2 / KAREA;
        double var = m2 - m1 * m1 / KAREA + EPS;
        float vf = (float)var;
        if (vf < 0.f) vf = 0.f;
        sden[tid] = sqrtf(vf);
    }
#undef RECT
    __syncthreads();

    // ---- peak phase ----
    double tsum = g_tstats[0], tsum2 = g_tstats[1];
    float stv  = sqrtf((float)(tsum2 - tsum * tsum / (double)NPIX + EPS));
    float cfix = (float)(sS1s * tsum / (double)NPIX);
    if (tid < NS) {
        float ccv = fabsf(g_cc[(size_t)b * NS + tid] - cfix);
        float v = ccv / (stv * sden[tid]);
        if (!(v == v)) v = 0.f;
        sncc[tid] = v;
    }
    __syncthreads();
    rv[tid] = (tid < NS) ? sncc[tid] : -1.f;
    ri[tid] = tid;
    __syncthreads();
    for (int st = 256; st > 0; st >>= 1) {
        if (tid < st) {
            float ov = rv[tid + st]; int oi = ri[tid + st];
            if (ov > rv[tid] || (ov == rv[tid] && oi < ri[tid])) { rv[tid] = ov; ri[tid] = oi; }
        }
        __syncthreads();
    }
    if (tid == 0) {
        int am = ri[0];
        int sx = am / SH, sy = am - sx * SH;
        float shx = -(float)(sx - MS);
        float shy = -(float)(sy - MS);
        int xm = sx - 1; if (xm < 0) xm += SH;
        int xp = sx + 1; if (xp > SH - 1) xp = SH - 1;
        int ym = sy - 1; if (ym < 0) ym += SH;
        int yp = sy + 1; if (yp > SH - 1) yp = SH - 1;
        float lxm = logf(sncc[xm * SH + sy]);
        float lxp = logf(sncc[xp * SH + sy]);
        float lym = logf(sncc[sx * SH + ym]);
        float lyp = logf(sncc[sx * SH + yp]);
        float lc4 = 4.f * logf(sncc[sx * SH + sy]);
        shx -= (lxm - lxp) / (2.f * lxm - lc4 + 2.f * lxp);
        shy -= (lym - lyp) / (2.f * lym - lc4 + 2.f * lyp);
        g_shift[b * 2 + 0] = shx;
        g_shift[b * 2 + 1] = shy;
    }
}

// ---------------- K4: bilinear warp (constant weights) + transposed store ----------------
__global__ void __launch_bounds__(256) k_warp(const float* __restrict__ fr,
                                              float* __restrict__ out) {
    int b = blockIdx.z;
    int X0 = blockIdx.x * 32, Y0 = blockIdx.y * 32;
    float dy = g_shift[b * 2 + 0];
    float dx = g_shift[b * 2 + 1];
    float fy = floorf(-dy), fx = floorf(-dx);
    int Ay = (int)fy, Ax = (int)fx;
    float wy = -dy - fy, wx = -dx - fx;
    float c00 = (1.f - wy) * (1.f - wx);
    float c01 = (1.f - wy) * wx;
    float c10 = wy * (1.f - wx);
    float c11 = wy * wx;

    __shared__ float sp[33 * 37];
    const float* im = fr + (size_t)b * NPIX;
    for (int idx = threadIdx.x; idx < 33 * 33; idx += 256) {
        int r = idx / 33, c = idx - r * 33;
        int gy = Y0 + Ay + r, gx = X0 + Ax + c;
        float v = (gy >= 0 && gy < HH && gx >= 0 && gx < WW) ? im[gy * WW + gx] : 0.f;
        sp[r * 37 + c] = v;
    }
    __syncthreads();

    int tx = threadIdx.x >> 3;
    int qy = (threadIdx.x & 7) << 2;
    float cA[5], cB[5];
#pragma unroll
    for (int i = 0; i < 5; ++i) {
        cA[i] = sp[(qy + i) * 37 + tx];
        cB[i] = sp[(qy + i) * 37 + tx + 1];
    }
    float4 o;
    o.x = fmaf(c00, cA[0], fmaf(c01, cB[0], fmaf(c10, cA[1], c11 * cB[1])));
    o.y = fmaf(c00, cA[1], fmaf(c01, cB[1], fmaf(c10, cA[2], c11 * cB[2])));
    o.z = fmaf(c00, cA[2], fmaf(c01, cB[2], fmaf(c10, cA[3], c11 * cB[3])));
    o.w = fmaf(c00, cA[3], fmaf(c01, cB[3], fmaf(c10, cA[4], c11 * cB[4])));
    *(float4*)(out + (size_t)b * NPIX + (size_t)(X0 + tx) * HH + Y0 + qy) = o;
}

// ---------------- launch ----------------
extern "C" void kernel_launch(void* const* d_in, const int* in_sizes, int n_in,
                              void* d_out, int out_size) {
    const float* fr = (const float*)d_in[0];
    const float* tp = (const float*)d_in[1];
    if (n_in >= 2 && in_sizes[0] < in_sizes[1]) { const float* t = fr; fr = tp; tp = t; }
    float* out = (float*)d_out;

    cudaFuncSetAttribute(k_corr,      cudaFuncAttributeMaxDynamicSharedMemorySize, SMEM_CORR);
    cudaFuncSetAttribute(k_statspeak, cudaFuncAttributeMaxDynamicSharedMemorySize, SMEM_SP);

    k_colpart<<<dim3(NB + 1, 8), 512>>>(fr, tp);
    k_corr<<<dim3(NBAND, 8), CTH, SMEM_CORR>>>(fr, tp);
    k_statspeak<<<NB, 512, SMEM_SP>>>(fr);
    k_warp<<<dim3(16, 16, NB), 256>>>(fr, out);
}

// round 13
// speedup vs baseline: 1.0038x; 1.0038x over previous
#include <cuda_runtime.h>
#include <math.h>

#define HH 512
#define WW 512
#define NB 32
#define MS 10
#define SH 21            // 2*MS+1
#define NS 441           // SH*SH
#define NPIX (HH*WW)     // 262144
#define KAREA (492.0*492.0)
#define EPS 1e-8

#define TBAND 14                 // image rows per band
#define NBAND 37                 // 37*14 = 518 >= 512
#define TROWS 34                 // TBAND + 20
#define TCOLS 532
#define ISTR 516
#define CTH 294                  // 21 p-values x 14 rows
#define SMEM_CORR ((TROWS*TCOLS + TBAND*ISTR) * 4) // 101248
#define SMEM_SP (40*512*4)

// ---------------- scratch ----------------
__device__ double g_tstats[2];
__device__ double g_colP1[NB*8*WW];        // per-slab column sums
__device__ double g_colP2[NB*8*WW];
__device__ float  g_cc[NB*NS];             // accumulated correlations
__device__ float  g_shift[NB*2];

// ---------------- K1: per-slab column sums + template stats + zero g_cc ----------------
__global__ void __launch_bounds__(512) k_colpart(const float* __restrict__ fr,
                                                 const float* __restrict__ tp) {
    int b = blockIdx.x;          // 0..NB ; b==NB -> template/zero duty
    int slab = blockIdx.y;       // 0..7
    int x = threadIdx.x;         // 512
    if (b == NB) {
        int base = slab * (NB * NS / 8);
        for (int i = x; i < NB * NS / 8; i += 512) g_cc[base + i] = 0.f;
        if (slab != 0) return;
        __shared__ double r1[512], r2[512];
        double c1 = 0.0, c2d = 0.0;
        for (int s = 0; s < 8; ++s) {
            float a1 = 0.f, a2 = 0.f, b1 = 0.f, b2 = 0.f;
#pragma unroll 4
            for (int y = s * 64; y < s * 64 + 64; y += 2) {
                float v0 = tp[y * WW + x];
                float v1 = tp[(y + 1) * WW + x];
                a1 += v0; b1 += v1;
                a2 = fmaf(v0, v0, a2); b2 = fmaf(v1, v1, b2);
            }
            c1  += (double)a1 + (double)b1;
            c2d += (double)a2 + (double)b2;
        }
        r1[x] = c1; r2[x] = c2d;
        __syncthreads();
        for (int st = 256; st > 0; st >>= 1) {
            if (x < st) { r1[x] += r1[x + st]; r2[x] += r2[x + st]; }
            __syncthreads();
        }
        if (x == 0) { g_tstats[0] = r1[0]; g_tstats[1] = r2[0]; }
        return;
    }
    const float* src = fr + (size_t)b * NPIX;
    int y0 = slab * 64;
    float s1a = 0.f, s1b = 0.f, s2a = 0.f, s2b = 0.f;
#pragma unroll 4
    for (int y = y0; y < y0 + 64; y += 2) {
        float v0 = src[y * WW + x];
        float v1 = src[(y + 1) * WW + x];
        s1a += v0; s1b += v1;
        s2a = fmaf(v0, v0, s2a); s2b = fmaf(v1, v1, s2b);
    }
    g_colP1[((size_t)b * 8 + slab) * WW + x] = (double)s1a + (double)s1b;
    g_colP2[((size_t)b * 8 + slab) * WW + x] = (double)s2a + (double)s2b;
}

// ---------------- K2: the correlation (hot kernel; R11 inner loop, frozen) ----------------
template<int SLOT>
__device__ __forceinline__ float wslot(const float4* w) {
    return ((SLOT & 3) == 0) ? w[(SLOT >> 2) & 7].x
         : ((SLOT & 3) == 1) ? w[(SLOT >> 2) & 7].y
         : ((SLOT & 3) == 2) ? w[(SLOT >> 2) & 7].z
                             : w[(SLOT >> 2) & 7].w;
}

template<int X, int J> struct FmaJ {
    static __device__ __forceinline__ void run(float v, const float4* w, float* acc) {
        acc[J] = fmaf(v, wslot<(X + 20 - J) & 31>(w), acc[J]);
        FmaJ<X, J + 1>::run(v, w, acc);
    }
};
template<int X> struct FmaJ<X, SH> {
    static __device__ __forceinline__ void run(float, const float4*, float*) {}
};

template<int SG, bool LAST> struct Step {
    static __device__ __forceinline__ void run(const float* __restrict__ tr,
                                               const float* __restrict__ ir,
                                               float4* w, float4* iv, float* acc) {
        iv[(SG + 1) & 1] = *(const float4*)(ir + 4 * SG + 4);   // prefetch next 4 px
        FmaJ<4 * SG + 0, 0>::run(iv[SG & 1].x, w, acc);
        FmaJ<4 * SG + 1, 0>::run(iv[SG & 1].y, w, acc);
        FmaJ<4 * SG + 2, 0>::run(iv[SG & 1].z, w, acc);
        FmaJ<4 * SG + 3, 0>::run(iv[SG & 1].w, w, acc);
        if (!LAST || SG <= 4)
            w[SG] = *(const float4*)(tr + 4 * SG + 32);         // refill dead quad
        Step<SG + 1, LAST>::run(tr, ir, w, iv, acc);
    }
};
template<bool LAST> struct Step<8, LAST> {
    static __device__ __forceinline__ void run(const float*, const float*,
                                               float4*, float4*, float*) {}
};

__global__ void __launch_bounds__(CTH, 2)
k_corr(const float* __restrict__ fr, const float* __restrict__ tp) {
    int band = blockIdx.x;                  // 0..36
    int fg   = blockIdx.y;                  // 0..7 (4 frames each)
    int y0 = band * TBAND;
    extern __shared__ float sm[];
    float* sm_t = sm;                       // TROWS x TCOLS
    float* sm_i = sm + TROWS * TCOLS;       // TBAND x ISTR
    int tid = threadIdx.x;

    // template tile once per block (shared by 4 frames); wrapped rows/cols
    for (int idx = tid; idx < TROWS * 256; idx += CTH) {
        int r = idx >> 8, c2 = idx & 255;
        int gy = (y0 - MS + r) & (HH - 1);
        float2 v = *(const float2*)(tp + gy * WW + 2 * c2);
        *(float2*)(sm_t + r * TCOLS + 10 + 2 * c2) = v;
    }
    for (int idx = tid; idx < TROWS * 20; idx += CTH) {
        int r = idx / 20, e = idx - r * 20;
        int c = (e < 10) ? e : (e + 512);
        int gy = (y0 - MS + r) & (HH - 1);
        int gx = (c - 10) & (WW - 1);
        sm_t[r * TCOLS + c] = tp[gy * WW + gx];
    }

    int yl = tid % TBAND;                   // image row in band
    int p  = tid / TBAND;                   // shift-row index 0..20
    const float* trow0 = sm_t + (yl + 2 * MS - p) * TCOLS;
    const float* irow0 = sm_i + yl * ISTR;

    for (int f = 0; f < 4; ++f) {
        int b = fg * 4 + f;
        const float* im = fr + (size_t)b * NPIX + (size_t)y0 * WW;
        __syncthreads();                    // sred of prev frame fully consumed
        for (int idx = tid; idx < TBAND * 128; idx += CTH) {
            int r = idx >> 7, c4 = idx & 127;
            float4 v;
            if (y0 + r < HH) v = *(const float4*)(im + r * WW + 4 * c4);
            else             v = make_float4(0.f, 0.f, 0.f, 0.f);
            *(float4*)(sm_i + r * ISTR + 4 * c4) = v;
        }
        __syncthreads();

        float acc[SH];
#pragma unroll
        for (int j = 0; j < SH; ++j) acc[j] = 0.f;
        float4 w[8];
#pragma unroll
        for (int m = 0; m < 8; ++m) w[m] = *(const float4*)(trow0 + 4 * m);
        float4 iv[2];
        iv[0] = *(const float4*)irow0;

        const float* tr = trow0;
        const float* ir = irow0;
#pragma unroll 1
        for (int it = 0; it < 15; ++it) {
            Step<0, false>::run(tr, ir, w, iv, acc);
            tr += 32; ir += 32;
        }
        Step<0, true>::run(tr, ir, w, iv, acc);

        __syncthreads();                    // all reads of sm_i done
        float* sred = sm_i;                 // reuse image buffer: 441*14 floats
#pragma unroll
        for (int j = 0; j < SH; ++j) sred[(p * SH + j) * TBAND + yl] = acc[j];
        __syncthreads();
        for (int s = tid; s < NS; s += CTH) {
            float v = 0.f;
#pragma unroll
            for (int k = 0; k < TBAND; ++k) v += sred[s * TBAND + k];
            atomicAdd(&g_cc[(size_t)b * NS + s], v);
        }
    }
}

// ---------------- K3: denominators + ncc + argmax + subpixel (fused) ----------------
__global__ void __launch_bounds__(512) k_statspeak(const float* __restrict__ fr) {
    __shared__ double scol1[512], scol2[512];
    __shared__ double srow1[40], srow2[40];
    __shared__ double rowPre1[41], rowPre2[41];
    __shared__ double colPre1[21], colPre2[21];
    __shared__ double colSuf1[21], colSuf2[21];
    __shared__ double spart1[16], spart2[16];
    __shared__ double sS1s, sS2s;
    __shared__ float PP1[41*41], PP2[41*41];
    __shared__ float sden[NS];
    __shared__ float sncc[NS];
    __shared__ float rv[512];
    __shared__ int   ri[512];
    extern __shared__ float sedge[];         // 40*512

    int b = blockIdx.x, tid = threadIdx.x;   // 512 threads
    {
        double c1 = 0.0, c2d = 0.0;
#pragma unroll
        for (int s = 0; s < 8; ++s) {
            c1  += g_colP1[((size_t)b * 8 + s) * WW + tid];
            c2d += g_colP2[((size_t)b * 8 + s) * WW + tid];
        }
        scol1[tid] = c1; scol2[tid] = c2d;
    }
    const float* im = fr + (size_t)b * NPIX;
    for (int idx = tid; idx < 40 * 512; idx += 512) {
        int r = idx >> 9, c = idx & 511;
        int y = (r < 20) ? r : (472 + r);
        sedge[idx] = im[y * WW + c];
    }
    __syncthreads();

    int wid = tid >> 5, lane = tid & 31;
    for (int r = wid; r < 40; r += 16) {
        double a = 0.0, c2 = 0.0;
        for (int c = lane; c < 512; c += 32) {
            double v = (double)sedge[r * 512 + c];
            a += v; c2 += v * v;
        }
#pragma unroll
        for (int s = 16; s > 0; s >>= 1) {
            a  += __shfl_down_sync(0xffffffffu, a, s);
            c2 += __shfl_down_sync(0xffffffffu, c2, s);
        }
        if (lane == 0) { srow1[r] = a; srow2[r] = c2; }
    }
    for (int idx = tid; idx < 41 * 41; idx += 512) { PP1[idx] = 0.f; PP2[idx] = 0.f; }
    __syncthreads();

    for (int idx = tid; idx < 1600; idx += 512) {
        int r = idx / 40, cc = idx - r * 40;
        int col = (cc < 20) ? cc : (472 + cc);
        float v = sedge[r * 512 + col];
        PP1[(r + 1) * 41 + cc + 1] = v;
        PP2[(r + 1) * 41 + cc + 1] = v * v;
    }
    {
        double a = scol1[tid], c2 = scol2[tid];
#pragma unroll
        for (int s = 16; s > 0; s >>= 1) {
            a  += __shfl_down_sync(0xffffffffu, a, s);
            c2 += __shfl_down_sync(0xffffffffu, c2, s);
        }
        if (lane == 0) { spart1[wid] = a; spart2[wid] = c2; }
    }
    __syncthreads();

    if (tid < 41) {
        float a = 0.f, c2 = 0.f;
        for (int c = 0; c < 41; ++c) {
            a  += PP1[tid * 41 + c]; PP1[tid * 41 + c] = a;
            c2 += PP2[tid * 41 + c]; PP2[tid * 41 + c] = c2;
        }
    }
    if (tid == 64)  { double a = 0; rowPre1[0] = 0; for (int r = 0; r < 40; ++r) { a += srow1[r]; rowPre1[r+1] = a; } }
    if (tid == 96)  { double a = 0; rowPre2[0] = 0; for (int r = 0; r < 40; ++r) { a += srow2[r]; rowPre2[r+1] = a; } }
    if (tid == 128) { double a = 0; colPre1[0] = 0; for (int c = 0; c < 20; ++c) { a += scol1[c]; colPre1[c+1] = a; } }
    if (tid == 160) { double a = 0; colPre2[0] = 0; for (int c = 0; c < 20; ++c) { a += scol2[c]; colPre2[c+1] = a; } }
    if (tid == 192) { double a = 0; colSuf1[20] = 0; for (int j = 19; j >= 0; --j) { a += scol1[492+j]; colSuf1[j] = a; } }
    if (tid == 224) { double a = 0; colSuf2[20] = 0; for (int j = 19; j >= 0; --j) { a += scol2[492+j]; colSuf2[j] = a; } }
    if (tid == 256) { double a = 0; for (int w = 0; w < 16; ++w) a += spart1[w]; sS1s = a; }
    if (tid == 288) { double a = 0; for (int w = 0; w < 16; ++w) a += spart2[w]; sS2s = a; }
    __syncthreads();

    if (tid < 41) {
        float a = 0.f, c2 = 0.f;
        for (int r = 0; r < 41; ++r) {
            a  += PP1[r * 41 + tid]; PP1[r * 41 + tid] = a;
            c2 += PP2[r * 41 + tid]; PP2[r * 41 + tid] = c2;
        }
    }
    __syncthreads();

#define RECT(PP, r0, r1, c0, c1) \
    (PP[(r1)*41+(c1)] - PP[(r0)*41+(c1)] - PP[(r1)*41+(c0)] + PP[(r0)*41+(c0)])
    if (tid < NS) {
        int p = tid / SH, j = tid - p * SH;
        double rsum1 = rowPre1[p] + (rowPre1[40] - rowPre1[p + 20]);
        double rsum2 = rowPre2[p] + (rowPre2[40] - rowPre2[p + 20]);
        double csum1 = colPre1[j] + colSuf1[j];
        double csum2 = colPre2[j] + colSuf2[j];
        float q1 = RECT(PP1, 0, p, 0, j) + RECT(PP1, 0, p, 20 + j, 40)
                 + RECT(PP1, p + 20, 40, 0, j) + RECT(PP1, p + 20, 40, 20 + j, 40);
        float q2 = RECT(PP2, 0, p, 0, j) + RECT(PP2, 0, p, 20 + j, 40)
                 + RECT(PP2, p + 20, 40, 0, j) + RECT(PP2, p + 20, 40, 20 + j, 40);
        double w1 = sS1s - rsum1 - csum1 + (double)q1;
        double w2 = sS2s - rsum2 - csum2 + (double)q2;
        double m1 = w1 / KAREA;
        double m2 = w2 / KAREA;
        double var = m2 - m1 * m1 / KAREA + EPS;
        float vf = (float)var;
        if (vf < 0.f) vf = 0.f;
        sden[tid] = sqrtf(vf);
    }
#undef RECT
    __syncthreads();

    // ---- peak phase ----
    double tsum = g_tstats[0], tsum2 = g_tstats[1];
    float stv  = sqrtf((float)(tsum2 - tsum * tsum / (double)NPIX + EPS));
    float cfix = (float)(sS1s * tsum / (double)NPIX);
    if (tid < NS) {
        float ccv = fabsf(g_cc[(size_t)b * NS + tid] - cfix);
        float v = ccv / (stv * sden[tid]);
        if (!(v == v)) v = 0.f;
        sncc[tid] = v;
    }
    __syncthreads();
    rv[tid] = (tid < NS) ? sncc[tid] : -1.f;
    ri[tid] = tid;
    __syncthreads();
    for (int st = 256; st > 0; st >>= 1) {
        if (tid < st) {
            float ov = rv[tid + st]; int oi = ri[tid + st];
            if (ov > rv[tid] || (ov == rv[tid] && oi < ri[tid])) { rv[tid] = ov; ri[tid] = oi; }
        }
        __syncthreads();
    }
    if (tid == 0) {
        int am = ri[0];
        int sx = am / SH, sy = am - sx * SH;
        float shx = -(float)(sx - MS);
        float shy = -(float)(sy - MS);
        int xm = sx - 1; if (xm < 0) xm += SH;
        int xp = sx + 1; if (xp > SH - 1) xp = SH - 1;
        int ym = sy - 1; if (ym < 0) ym += SH;
        int yp = sy + 1; if (yp > SH - 1) yp = SH - 1;
        float lxm = logf(sncc[xm * SH + sy]);
        float lxp = logf(sncc[xp * SH + sy]);
        float lym = logf(sncc[sx * SH + ym]);
        float lyp = logf(sncc[sx * SH + yp]);
        float lc4 = 4.f * logf(sncc[sx * SH + sy]);
        shx -= (lxm - lxp) / (2.f * lxm - lc4 + 2.f * lxp);
        shy -= (lym - lyp) / (2.f * lym - lc4 + 2.f * lyp);
        g_shift[b * 2 + 0] = shx;
        g_shift[b * 2 + 1] = shy;
    }
}

// ---------------- K4: bilinear warp (constant weights) + transposed store ----------------
__global__ void __launch_bounds__(256) k_warp(const float* __restrict__ fr,
                                              float* __restrict__ out) {
    int b = blockIdx.z;
    int X0 = blockIdx.x * 32, Y0 = blockIdx.y * 32;
    float dy = g_shift[b * 2 + 0];
    float dx = g_shift[b * 2 + 1];
    float fy = floorf(-dy), fx = floorf(-dx);
    int Ay = (int)fy, Ax = (int)fx;
    float wy = -dy - fy, wx = -dx - fx;
    float c00 = (1.f - wy) * (1.f - wx);
    float c01 = (1.f - wy) * wx;
    float c10 = wy * (1.f - wx);
    float c11 = wy * wx;

    __shared__ float sp[33 * 37];
    const float* im = fr + (size_t)b * NPIX;
    for (int idx = threadIdx.x; idx < 33 * 33; idx += 256) {
        int r = idx / 33, c = idx - r * 33;
        int gy = Y0 + Ay + r, gx = X0 + Ax + c;
        float v = (gy >= 0 && gy < HH && gx >= 0 && gx < WW) ? im[gy * WW + gx] : 0.f;
        sp[r * 37 + c] = v;
    }
    __syncthreads();

    int tx = threadIdx.x >> 3;
    int qy = (threadIdx.x & 7) << 2;
    float cA[5], cB[5];
#pragma unroll
    for (int i = 0; i < 5; ++i) {
        cA[i] = sp[(qy + i) * 37 + tx];
        cB[i] = sp[(qy + i) * 37 + tx + 1];
    }
    float4 o;
    o.x = fmaf(c00, cA[0], fmaf(c01, cB[0], fmaf(c10, cA[1], c11 * cB[1])));
    o.y = fmaf(c00, cA[1], fmaf(c01, cB[1], fmaf(c10, cA[2], c11 * cB[2])));
    o.z = fmaf(c00, cA[2], fmaf(c01, cB[2], fmaf(c10, cA[3], c11 * cB[3])));
    o.w = fmaf(c00, cA[3], fmaf(c01, cB[3], fmaf(c10, cA[4], c11 * cB[4])));
    *(float4*)(out + (size_t)b * NPIX + (size_t)(X0 + tx) * HH + Y0 + qy) = o;
}

// ---------------- launch ----------------
extern "C" void kernel_launch(void* const* d_in, const int* in_sizes, int n_in,
                              void* d_out, int out_size) {
    const float* fr = (const float*)d_in[0];
    const float* tp = (const float*)d_in[1];
    if (n_in >= 2 && in_sizes[0] < in_sizes[1]) { const float* t = fr; fr = tp; tp = t; }
    float* out = (float*)d_out;

    cudaFuncSetAttribute(k_corr,      cudaFuncAttributeMaxDynamicSharedMemorySize, SMEM_CORR);
    cudaFuncSetAttribute(k_statspeak, cudaFuncAttributeMaxDynamicSharedMemorySize, SMEM_SP);

    k_colpart<<<dim3(NB + 1, 8), 512>>>(fr, tp);
    k_corr<<<dim3(NBAND, 8), CTH, SMEM_CORR>>>(fr, tp);
    k_statspeak<<<NB, 512, SMEM_SP>>>(fr);
    k_warp<<<dim3(16, 16, NB), 256>>>(fr, out);
}

// round 14
// speedup vs baseline: 1.0449x; 1.0409x over previous
#include <cuda_runtime.h>
#include <math.h>

#define HH 512
#define WW 512
#define NB 32
#define MS 10
#define SH 21            // 2*MS+1
#define NS 441           // SH*SH
#define NPIX (HH*WW)     // 262144
#define KAREA (492.0*492.0)
#define EPS 1e-8

#define TBAND 14                 // image rows per band
#define NBAND 37                 // 37*14 = 518 >= 512
#define TROWS 34                 // TBAND + 20
#define TCOLS 532
#define ISTR 516
#define CTH 294                  // 21 p-values x 14 rows
#define NLD ((TBAND*128 + CTH - 1) / CTH)          // 7 float4 loads/thread
#define SMEM_CORR ((TROWS*TCOLS + TBAND*ISTR) * 4) // 101248
#define SMEM_SP (40*512*4)

// ---------------- scratch ----------------
__device__ double g_tpart1[8], g_tpart2[8];    // per-slab template stats
__device__ double g_colP1[NB*8*WW];            // per-slab column sums
__device__ double g_colP2[NB*8*WW];
__device__ float  g_cc[NB*NS];                 // accumulated correlations
__device__ float  g_shift[NB*2];

// ---------------- K1: per-slab column sums + template stats + zero g_cc ----------------
__global__ void __launch_bounds__(512) k_colpart(const float* __restrict__ fr,
                                                 const float* __restrict__ tp) {
    int b = blockIdx.x;          // 0..NB ; b==NB -> template slab duty
    int slab = blockIdx.y;       // 0..7
    int x = threadIdx.x;         // 512
    int y0 = slab * 64;
    const float* src = (b < NB) ? (fr + (size_t)b * NPIX) : tp;

    float s1a = 0.f, s1b = 0.f, s2a = 0.f, s2b = 0.f;
#pragma unroll 4
    for (int y = y0; y < y0 + 64; y += 2) {
        float v0 = src[y * WW + x];
        float v1 = src[(y + 1) * WW + x];
        s1a += v0; s1b += v1;
        s2a = fmaf(v0, v0, s2a); s2b = fmaf(v1, v1, s2b);
    }
    double d1 = (double)s1a + (double)s1b;
    double d2 = (double)s2a + (double)s2b;

    if (b < NB) {
        g_colP1[((size_t)b * 8 + slab) * WW + x] = d1;
        g_colP2[((size_t)b * 8 + slab) * WW + x] = d2;
    } else {
        __shared__ double r1[512], r2[512];
        r1[x] = d1; r2[x] = d2;
        __syncthreads();
        for (int st = 256; st > 0; st >>= 1) {
            if (x < st) { r1[x] += r1[x + st]; r2[x] += r2[x + st]; }
            __syncthreads();
        }
        if (x == 0) { g_tpart1[slab] = r1[0]; g_tpart2[slab] = r2[0]; }
        // zero 1/8 of g_cc
        int base = slab * (NB * NS / 8);
        for (int i = x; i < NB * NS / 8; i += 512) g_cc[base + i] = 0.f;
    }
}

// ---------------- K2: the correlation (hot kernel; R11 inner loop, frozen) ----------------
template<int SLOT>
__device__ __forceinline__ float wslot(const float4* w) {
    return ((SLOT & 3) == 0) ? w[(SLOT >> 2) & 7].x
         : ((SLOT & 3) == 1) ? w[(SLOT >> 2) & 7].y
         : ((SLOT & 3) == 2) ? w[(SLOT >> 2) & 7].z
                             : w[(SLOT >> 2) & 7].w;
}

template<int X, int J> struct FmaJ {
    static __device__ __forceinline__ void run(float v, const float4* w, float* acc) {
        acc[J] = fmaf(v, wslot<(X + 20 - J) & 31>(w), acc[J]);
        FmaJ<X, J + 1>::run(v, w, acc);
    }
};
template<int X> struct FmaJ<X, SH> {
    static __device__ __forceinline__ void run(float, const float4*, float*) {}
};

template<int SG, bool LAST> struct Step {
    static __device__ __forceinline__ void run(const float* __restrict__ tr,
                                               const float* __restrict__ ir,
                                               float4* w, float4* iv, float* acc) {
        iv[(SG + 1) & 1] = *(const float4*)(ir + 4 * SG + 4);   // prefetch next 4 px
        FmaJ<4 * SG + 0, 0>::run(iv[SG & 1].x, w, acc);
        FmaJ<4 * SG + 1, 0>::run(iv[SG & 1].y, w, acc);
        FmaJ<4 * SG + 2, 0>::run(iv[SG & 1].z, w, acc);
        FmaJ<4 * SG + 3, 0>::run(iv[SG & 1].w, w, acc);
        if (!LAST || SG <= 4)
            w[SG] = *(const float4*)(tr + 4 * SG + 32);         // refill dead quad
        Step<SG + 1, LAST>::run(tr, ir, w, iv, acc);
    }
};
template<bool LAST> struct Step<8, LAST> {
    static __device__ __forceinline__ void run(const float*, const float*,
                                               float4*, float4*, float*) {}
};

__device__ __forceinline__ void pf_load(float4* pf, const float* __restrict__ im,
                                        int y0, int tid) {
#pragma unroll
    for (int k = 0; k < NLD; ++k) {
        int idx = tid + k * CTH;
        float4 v = make_float4(0.f, 0.f, 0.f, 0.f);
        if (idx < TBAND * 128) {
            int r = idx >> 7, c4 = idx & 127;
            if (y0 + r < HH) v = *(const float4*)(im + r * WW + 4 * c4);
        }
        pf[k] = v;
    }
}

__global__ void __launch_bounds__(CTH, 2)
k_corr(const float* __restrict__ fr, const float* __restrict__ tp) {
    int band = blockIdx.x;                  // 0..36
    int fg   = blockIdx.y;                  // 0..7 (4 frames each)
    int y0 = band * TBAND;
    extern __shared__ float sm[];
    float* sm_t = sm;                       // TROWS x TCOLS
    float* sm_i = sm + TROWS * TCOLS;       // TBAND x ISTR
    int tid = threadIdx.x;

    // template tile once per block (shared by 4 frames); wrapped rows/cols
    for (int idx = tid; idx < TROWS * 256; idx += CTH) {
        int r = idx >> 8, c2 = idx & 255;
        int gy = (y0 - MS + r) & (HH - 1);
        float2 v = *(const float2*)(tp + gy * WW + 2 * c2);
        *(float2*)(sm_t + r * TCOLS + 10 + 2 * c2) = v;
    }
    for (int idx = tid; idx < TROWS * 20; idx += CTH) {
        int r = idx / 20, e = idx - r * 20;
        int c = (e < 10) ? e : (e + 512);
        int gy = (y0 - MS + r) & (HH - 1);
        int gx = (c - 10) & (WW - 1);
        sm_t[r * TCOLS + c] = tp[gy * WW + gx];
    }

    int yl = tid % TBAND;                   // image row in band
    int p  = tid / TBAND;                   // shift-row index 0..20
    const float* trow0 = sm_t + (yl + 2 * MS - p) * TCOLS;
    const float* irow0 = sm_i + yl * ISTR;
    int b0 = fg * 4;

    float4 pf[NLD];
    pf_load(pf, fr + (size_t)b0 * NPIX + (size_t)y0 * WW, y0, tid);

    for (int f = 0; f < 4; ++f) {
        __syncthreads();                    // sred of prev frame fully consumed
#pragma unroll
        for (int k = 0; k < NLD; ++k) {     // store prefetched image band
            int idx = tid + k * CTH;
            if (idx < TBAND * 128) {
                int r = idx >> 7, c4 = idx & 127;
                *(float4*)(sm_i + r * ISTR + 4 * c4) = pf[k];
            }
        }
        __syncthreads();
        if (f < 3)                          // overlap next frame's DRAM reads
            pf_load(pf, fr + (size_t)(b0 + f + 1) * NPIX + (size_t)y0 * WW, y0, tid);

        float acc[SH];
#pragma unroll
        for (int j = 0; j < SH; ++j) acc[j] = 0.f;
        float4 w[8];
#pragma unroll
        for (int m = 0; m < 8; ++m) w[m] = *(const float4*)(trow0 + 4 * m);
        float4 iv[2];
        iv[0] = *(const float4*)irow0;

        const float* tr = trow0;
        const float* ir = irow0;
#pragma unroll 1
        for (int it = 0; it < 15; ++it) {
            Step<0, false>::run(tr, ir, w, iv, acc);
            tr += 32; ir += 32;
        }
        Step<0, true>::run(tr, ir, w, iv, acc);

        __syncthreads();                    // all reads of sm_i done
        float* sred = sm_i;                 // reuse image buffer: 441*14 floats
#pragma unroll
        for (int j = 0; j < SH; ++j) sred[(p * SH + j) * TBAND + yl] = acc[j];
        __syncthreads();
        for (int s = tid; s < NS; s += CTH) {
            float v = 0.f;
#pragma unroll
            for (int k = 0; k < TBAND; ++k) v += sred[s * TBAND + k];
            atomicAdd(&g_cc[(size_t)(b0 + f) * NS + s], v);
        }
    }
}

// ---------------- K3: denominators + ncc + argmax + subpixel (fused) ----------------
__global__ void __launch_bounds__(512) k_statspeak(const float* __restrict__ fr) {
    __shared__ double scol1[512], scol2[512];
    __shared__ double srow1[40], srow2[40];
    __shared__ double rowPre1[41], rowPre2[41];
    __shared__ double colPre1[21], colPre2[21];
    __shared__ double colSuf1[21], colSuf2[21];
    __shared__ double spart1[16], spart2[16];
    __shared__ double sS1s, sS2s;
    __shared__ float PP1[41*41], PP2[41*41];
    __shared__ float sden[NS];
    __shared__ float sncc[NS];
    __shared__ float rv[512];
    __shared__ int   ri[512];
    extern __shared__ float sedge[];         // 40*512

    int b = blockIdx.x, tid = threadIdx.x;   // 512 threads
    {
        double c1 = 0.0, c2d = 0.0;
#pragma unroll
        for (int s = 0; s < 8; ++s) {
            c1  += g_colP1[((size_t)b * 8 + s) * WW + tid];
            c2d += g_colP2[((size_t)b * 8 + s) * WW + tid];
        }
        scol1[tid] = c1; scol2[tid] = c2d;
    }
    const float* im = fr + (size_t)b * NPIX;
    for (int idx = tid; idx < 40 * 512; idx += 512) {
        int r = idx >> 9, c = idx & 511;
        int y = (r < 20) ? r : (472 + r);
        sedge[idx] = im[y * WW + c];
    }
    __syncthreads();

    int wid = tid >> 5, lane = tid & 31;
    for (int r = wid; r < 40; r += 16) {
        double a = 0.0, c2 = 0.0;
        for (int c = lane; c < 512; c += 32) {
            double v = (double)sedge[r * 512 + c];
            a += v; c2 += v * v;
        }
#pragma unroll
        for (int s = 16; s > 0; s >>= 1) {
            a  += __shfl_down_sync(0xffffffffu, a, s);
            c2 += __shfl_down_sync(0xffffffffu, c2, s);
        }
        if (lane == 0) { srow1[r] = a; srow2[r] = c2; }
    }
    for (int idx = tid; idx < 41 * 41; idx += 512) { PP1[idx] = 0.f; PP2[idx] = 0.f; }
    __syncthreads();

    for (int idx = tid; idx < 1600; idx += 512) {
        int r = idx / 40, cc = idx - r * 40;
        int col = (cc < 20) ? cc : (472 + cc);
        float v = sedge[r * 512 + col];
        PP1[(r + 1) * 41 + cc + 1] = v;
        PP2[(r + 1) * 41 + cc + 1] = v * v;
    }
    {
        double a = scol1[tid], c2 = scol2[tid];
#pragma unroll
        for (int s = 16; s > 0; s >>= 1) {
            a  += __shfl_down_sync(0xffffffffu, a, s);
            c2 += __shfl_down_sync(0xffffffffu, c2, s);
        }
        if (lane == 0) { spart1[wid] = a; spart2[wid] = c2; }
    }
    __syncthreads();

    if (tid < 41) {
        float a = 0.f, c2 = 0.f;
        for (int c = 0; c < 41; ++c) {
            a  += PP1[tid * 41 + c]; PP1[tid * 41 + c] = a;
            c2 += PP2[tid * 41 + c]; PP2[tid * 41 + c] = c2;
        }
    }
    if (tid == 64)  { double a = 0; rowPre1[0] = 0; for (int r = 0; r < 40; ++r) { a += srow1[r]; rowPre1[r+1] = a; } }
    if (tid == 96)  { double a = 0; rowPre2[0] = 0; for (int r = 0; r < 40; ++r) { a += srow2[r]; rowPre2[r+1] = a; } }
    if (tid == 128) { double a = 0; colPre1[0] = 0; for (int c = 0; c < 20; ++c) { a += scol1[c]; colPre1[c+1] = a; } }
    if (tid == 160) { double a = 0; colPre2[0] = 0; for (int c = 0; c < 20; ++c) { a += scol2[c]; colPre2[c+1] = a; } }
    if (tid == 192) { double a = 0; colSuf1[20] = 0; for (int j = 19; j >= 0; --j) { a += scol1[492+j]; colSuf1[j] = a; } }
    if (tid == 224) { double a = 0; colSuf2[20] = 0; for (int j = 19; j >= 0; --j) { a += scol2[492+j]; colSuf2[j] = a; } }
    if (tid == 256) { double a = 0; for (int w = 0; w < 16; ++w) a += spart1[w]; sS1s = a; }
    if (tid == 288) { double a = 0; for (int w = 0; w < 16; ++w) a += spart2[w]; sS2s = a; }
    __syncthreads();

    if (tid < 41) {
        float a = 0.f, c2 = 0.f;
        for (int r = 0; r < 41; ++r) {
            a  += PP1[r * 41 + tid]; PP1[r * 41 + tid] = a;
            c2 += PP2[r * 41 + tid]; PP2[r * 41 + tid] = c2;
        }
    }
    __syncthreads();

#define RECT(PP, r0, r1, c0, c1) \
    (PP[(r1)*41+(c1)] - PP[(r0)*41+(c1)] - PP[(r1)*41+(c0)] + PP[(r0)*41+(c0)])
    if (tid < NS) {
        int p = tid / SH, j = tid - p * SH;
        double rsum1 = rowPre1[p] + (rowPre1[40] - rowPre1[p + 20]);
        double rsum2 = rowPre2[p] + (rowPre2[40] - rowPre2[p + 20]);
        double csum1 = colPre1[j] + colSuf1[j];
        double csum2 = colPre2[j] + colSuf2[j];
        float q1 = RECT(PP1, 0, p, 0, j) + RECT(PP1, 0, p, 20 + j, 40)
                 + RECT(PP1, p + 20, 40, 0, j) + RECT(PP1, p + 20, 40, 20 + j, 40);
        float q2 = RECT(PP2, 0, p, 0, j) + RECT(PP2, 0, p, 20 + j, 40)
                 + RECT(PP2, p + 20, 40, 0, j) + RECT(PP2, p + 20, 40, 20 + j, 40);
        double w1 = sS1s - rsum1 - csum1 + (double)q1;
        double w2 = sS2s - rsum2 - csum2 + (double)q2;
        double m1 = w1 / KAREA;
        double m2 = w2 / KAREA;
        double var = m2 - m1 * m1 / KAREA + EPS;
        float vf = (float)var;
        if (vf < 0.f) vf = 0.f;
        sden[tid] = sqrtf(vf);
    }
#undef RECT
    __syncthreads();

    // ---- peak phase ----
    double tsum = 0.0, tsum2 = 0.0;
#pragma unroll
    for (int s = 0; s < 8; ++s) { tsum += g_tpart1[s]; tsum2 += g_tpart2[s]; }
    float stv  = sqrtf((float)(tsum2 - tsum * tsum / (double)NPIX + EPS));
    float cfix = (float)(sS1s * tsum / (double)NPIX);
    if (tid < NS) {
        float ccv = fabsf(g_cc[(size_t)b * NS + tid] - cfix);
        float v = ccv / (stv * sden[tid]);
        if (!(v == v)) v = 0.f;
        sncc[tid] = v;
    }
    __syncthreads();
    rv[tid] = (tid < NS) ? sncc[tid] : -1.f;
    ri[tid] = tid;
    __syncthreads();
    for (int st = 256; st > 0; st >>= 1) {
        if (tid < st) {
            float ov = rv[tid + st]; int oi = ri[tid + st];
            if (ov > rv[tid] || (ov == rv[tid] && oi < ri[tid])) { rv[tid] = ov; ri[tid] = oi; }
        }
        __syncthreads();
    }
    if (tid == 0) {
        int am = ri[0];
        int sx = am / SH, sy = am - sx * SH;
        float shx = -(float)(sx - MS);
        float shy = -(float)(sy - MS);
        int xm = sx - 1; if (xm < 0) xm += SH;
        int xp = sx + 1; if (xp > SH - 1) xp = SH - 1;
        int ym = sy - 1; if (ym < 0) ym += SH;
        int yp = sy + 1; if (yp > SH - 1) yp = SH - 1;
        float lxm = logf(sncc[xm * SH + sy]);
        float lxp = logf(sncc[xp * SH + sy]);
        float lym = logf(sncc[sx * SH + ym]);
        float lyp = logf(sncc[sx * SH + yp]);
        float lc4 = 4.f * logf(sncc[sx * SH + sy]);
        shx -= (lxm - lxp) / (2.f * lxm - lc4 + 2.f * lxp);
        shy -= (lym - lyp) / (2.f * lym - lc4 + 2.f * lyp);
        g_shift[b * 2 + 0] = shx;
        g_shift[b * 2 + 1] = shy;
    }
}

// ---------------- K4: bilinear warp (constant weights) + transposed store ----------------
__global__ void __launch_bounds__(256) k_warp(const float* __restrict__ fr,
                                              float* __restrict__ out) {
    int b = blockIdx.z;
    int X0 = blockIdx.x * 32, Y0 = blockIdx.y * 32;
    float dy = g_shift[b * 2 + 0];
    float dx = g_shift[b * 2 + 1];
    float fy = floorf(-dy), fx = floorf(-dx);
    int Ay = (int)fy, Ax = (int)fx;
    float wy = -dy - fy, wx = -dx - fx;
    float c00 = (1.f - wy) * (1.f - wx);
    float c01 = (1.f - wy) * wx;
    float c10 = wy * (1.f - wx);
    float c11 = wy * wx;

    __shared__ float sp[33 * 37];
    const float* im = fr + (size_t)b * NPIX;
    for (int idx = threadIdx.x; idx < 33 * 33; idx += 256) {
        int r = idx / 33, c = idx - r * 33;
        int gy = Y0 + Ay + r, gx = X0 + Ax + c;
        float v = (gy >= 0 && gy < HH && gx >= 0 && gx < WW) ? im[gy * WW + gx] : 0.f;
        sp[r * 37 + c] = v;
    }
    __syncthreads();

    int tx = threadIdx.x >> 3;
    int qy = (threadIdx.x & 7) << 2;
    float cA[5], cB[5];
#pragma unroll
    for (int i = 0; i < 5; ++i) {
        cA[i] = sp[(qy + i) * 37 + tx];
        cB[i] = sp[(qy + i) * 37 + tx + 1];
    }
    float4 o;
    o.x = fmaf(c00, cA[0], fmaf(c01, cB[0], fmaf(c10, cA[1], c11 * cB[1])));
    o.y = fmaf(c00, cA[1], fmaf(c01, cB[1], fmaf(c10, cA[2], c11 * cB[2])));
    o.z = fmaf(c00, cA[2], fmaf(c01, cB[2], fmaf(c10, cA[3], c11 * cB[3])));
    o.w = fmaf(c00, cA[3], fmaf(c01, cB[3], fmaf(c10, cA[4], c11 * cB[4])));
    *(float4*)(out + (size_t)b * NPIX + (size_t)(X0 + tx) * HH + Y0 + qy) = o;
}

// ---------------- launch ----------------
extern "C" void kernel_launch(void* const* d_in, const int* in_sizes, int n_in,
                              void* d_out, int out_size) {
    const float* fr = (const float*)d_in[0];
    const float* tp = (const float*)d_in[1];
    if (n_in >= 2 && in_sizes[0] < in_sizes[1]) { const float* t = fr; fr = tp; tp = t; }
    float* out = (float*)d_out;

    cudaFuncSetAttribute(k_corr,      cudaFuncAttributeMaxDynamicSharedMemorySize, SMEM_CORR);
    cudaFuncSetAttribute(k_statspeak, cudaFuncAttributeMaxDynamicSharedMemorySize, SMEM_SP);

    k_colpart<<<dim3(NB + 1, 8), 512>>>(fr, tp);
    k_corr<<<dim3(NBAND, 8), CTH, SMEM_CORR>>>(fr, tp);
    k_statspeak<<<NB, 512, SMEM_SP>>>(fr);
    k_warp<<<dim3(16, 16, NB), 256>>>(fr, out);
}

// round 15
// speedup vs baseline: 1.0602x; 1.0146x over previous
#include <cuda_runtime.h>
#include <math.h>

#define HH 512
#define WW 512
#define NB 32
#define MS 10
#define SH 21            // 2*MS+1
#define NS 441           // SH*SH
#define NPIX (HH*WW)     // 262144
#define KAREA (492.0*492.0)
#define EPS 1e-8

#define TBAND 14                 // image rows per band
#define NBAND 37                 // 37*14 = 518 >= 512
#define TROWS 34                 // TBAND + 20
#define TCOLS 532
#define ISTR 516
#define CTH 294                  // 21 p-values x 14 rows
#define SMEM_CORR ((TROWS*TCOLS + TBAND*ISTR) * 4) // 101248
#define SMEM_SP (40*512*4)

// ---------------- scratch ----------------
__device__ double g_tpart1[8], g_tpart2[8];    // per-slab template stats
__device__ double g_colP1[NB*8*WW];            // per-slab column sums
__device__ double g_colP2[NB*8*WW];
__device__ float  g_cc[NB*NS];                 // accumulated correlations
__device__ float  g_shift[NB*2];

// ---------------- K1: per-slab column sums + template stats + zero g_cc ----------------
__global__ void __launch_bounds__(512) k_colpart(const float* __restrict__ fr,
                                                 const float* __restrict__ tp) {
    int b = blockIdx.x;          // 0..NB ; b==NB -> template slab duty
    int slab = blockIdx.y;       // 0..7
    int x = threadIdx.x;         // 512
    int y0 = slab * 64;
    const float* src = (b < NB) ? (fr + (size_t)b * NPIX) : tp;

    float s1a = 0.f, s1b = 0.f, s2a = 0.f, s2b = 0.f;
#pragma unroll 4
    for (int y = y0; y < y0 + 64; y += 2) {
        float v0 = src[y * WW + x];
        float v1 = src[(y + 1) * WW + x];
        s1a += v0; s1b += v1;
        s2a = fmaf(v0, v0, s2a); s2b = fmaf(v1, v1, s2b);
    }
    double d1 = (double)s1a + (double)s1b;
    double d2 = (double)s2a + (double)s2b;

    if (b < NB) {
        g_colP1[((size_t)b * 8 + slab) * WW + x] = d1;
        g_colP2[((size_t)b * 8 + slab) * WW + x] = d2;
    } else {
        __shared__ double r1[512], r2[512];
        r1[x] = d1; r2[x] = d2;
        __syncthreads();
        for (int st = 256; st > 0; st >>= 1) {
            if (x < st) { r1[x] += r1[x + st]; r2[x] += r2[x + st]; }
            __syncthreads();
        }
        if (x == 0) { g_tpart1[slab] = r1[0]; g_tpart2[slab] = r2[0]; }
        // zero 1/8 of g_cc
        int base = slab * (NB * NS / 8);
        for (int i = x; i < NB * NS / 8; i += 512) g_cc[base + i] = 0.f;
    }
}

// ---------------- K2: the correlation (hot kernel; R11 verbatim, frozen) ----------------
template<int SLOT>
__device__ __forceinline__ float wslot(const float4* w) {
    return ((SLOT & 3) == 0) ? w[(SLOT >> 2) & 7].x
         : ((SLOT & 3) == 1) ? w[(SLOT >> 2) & 7].y
         : ((SLOT & 3) == 2) ? w[(SLOT >> 2) & 7].z
                             : w[(SLOT >> 2) & 7].w;
}

template<int X, int J> struct FmaJ {
    static __device__ __forceinline__ void run(float v, const float4* w, float* acc) {
        acc[J] = fmaf(v, wslot<(X + 20 - J) & 31>(w), acc[J]);
        FmaJ<X, J + 1>::run(v, w, acc);
    }
};
template<int X> struct FmaJ<X, SH> {
    static __device__ __forceinline__ void run(float, const float4*, float*) {}
};

template<int SG, bool LAST> struct Step {
    static __device__ __forceinline__ void run(const float* __restrict__ tr,
                                               const float* __restrict__ ir,
                                               float4* w, float4* iv, float* acc) {
        iv[(SG + 1) & 1] = *(const float4*)(ir + 4 * SG + 4);   // prefetch next 4 px
        FmaJ<4 * SG + 0, 0>::run(iv[SG & 1].x, w, acc);
        FmaJ<4 * SG + 1, 0>::run(iv[SG & 1].y, w, acc);
        FmaJ<4 * SG + 2, 0>::run(iv[SG & 1].z, w, acc);
        FmaJ<4 * SG + 3, 0>::run(iv[SG & 1].w, w, acc);
        if (!LAST || SG <= 4)
            w[SG] = *(const float4*)(tr + 4 * SG + 32);         // refill dead quad
        Step<SG + 1, LAST>::run(tr, ir, w, iv, acc);
    }
};
template<bool LAST> struct Step<8, LAST> {
    static __device__ __forceinline__ void run(const float*, const float*,
                                               float4*, float4*, float*) {}
};

__global__ void __launch_bounds__(CTH, 2)
k_corr(const float* __restrict__ fr, const float* __restrict__ tp) {
    int band = blockIdx.x;                  // 0..36
    int fg   = blockIdx.y;                  // 0..7 (4 frames each)
    int y0 = band * TBAND;
    extern __shared__ float sm[];
    float* sm_t = sm;                       // TROWS x TCOLS
    float* sm_i = sm + TROWS * TCOLS;       // TBAND x ISTR
    int tid = threadIdx.x;

    // template tile once per block (shared by 4 frames); wrapped rows/cols
    for (int idx = tid; idx < TROWS * 256; idx += CTH) {
        int r = idx >> 8, c2 = idx & 255;
        int gy = (y0 - MS + r) & (HH - 1);
        float2 v = *(const float2*)(tp + gy * WW + 2 * c2);
        *(float2*)(sm_t + r * TCOLS + 10 + 2 * c2) = v;
    }
    for (int idx = tid; idx < TROWS * 20; idx += CTH) {
        int r = idx / 20, e = idx - r * 20;
        int c = (e < 10) ? e : (e + 512);
        int gy = (y0 - MS + r) & (HH - 1);
        int gx = (c - 10) & (WW - 1);
        sm_t[r * TCOLS + c] = tp[gy * WW + gx];
    }

    int yl = tid % TBAND;                   // image row in band
    int p  = tid / TBAND;                   // shift-row index 0..20
    const float* trow0 = sm_t + (yl + 2 * MS - p) * TCOLS;
    const float* irow0 = sm_i + yl * ISTR;

    for (int f = 0; f < 4; ++f) {
        int b = fg * 4 + f;
        const float* im = fr + (size_t)b * NPIX + (size_t)y0 * WW;
        __syncthreads();                    // sred of prev frame fully consumed
        for (int idx = tid; idx < TBAND * 128; idx += CTH) {
            int r = idx >> 7, c4 = idx & 127;
            float4 v;
            if (y0 + r < HH) v = *(const float4*)(im + r * WW + 4 * c4);
            else             v = make_float4(0.f, 0.f, 0.f, 0.f);
            *(float4*)(sm_i + r * ISTR + 4 * c4) = v;
        }
        __syncthreads();

        float acc[SH];
#pragma unroll
        for (int j = 0; j < SH; ++j) acc[j] = 0.f;
        float4 w[8];
#pragma unroll
        for (int m = 0; m < 8; ++m) w[m] = *(const float4*)(trow0 + 4 * m);
        float4 iv[2];
        iv[0] = *(const float4*)irow0;

        const float* tr = trow0;
        const float* ir = irow0;
#pragma unroll 1
        for (int it = 0; it < 15; ++it) {
            Step<0, false>::run(tr, ir, w, iv, acc);
            tr += 32; ir += 32;
        }
        Step<0, true>::run(tr, ir, w, iv, acc);

        __syncthreads();                    // all reads of sm_i done
        float* sred = sm_i;                 // reuse image buffer: 441*14 floats
#pragma unroll
        for (int j = 0; j < SH; ++j) sred[(p * SH + j) * TBAND + yl] = acc[j];
        __syncthreads();
        for (int s = tid; s < NS; s += CTH) {
            float v = 0.f;
#pragma unroll
            for (int k = 0; k < TBAND; ++k) v += sred[s * TBAND + k];
            atomicAdd(&g_cc[(size_t)b * NS + s], v);
        }
    }
}

// ---------------- K3: denominators + ncc + argmax + subpixel (fused) ----------------
__global__ void __launch_bounds__(512) k_statspeak(const float* __restrict__ fr) {
    __shared__ double scol1[512], scol2[512];
    __shared__ double srow1[40], srow2[40];
    __shared__ double rowPre1[41], rowPre2[41];
    __shared__ double colPre1[21], colPre2[21];
    __shared__ double colSuf1[21], colSuf2[21];
    __shared__ double spart1[16], spart2[16];
    __shared__ double sS1s, sS2s;
    __shared__ float PP1[41*41], PP2[41*41];
    __shared__ float sden[NS];
    __shared__ float sncc[NS];
    __shared__ float rv[512];
    __shared__ int   ri[512];
    extern __shared__ float sedge[];         // 40*512

    int b = blockIdx.x, tid = threadIdx.x;   // 512 threads
    {
        double c1 = 0.0, c2d = 0.0;
#pragma unroll
        for (int s = 0; s < 8; ++s) {
            c1  += g_colP1[((size_t)b * 8 + s) * WW + tid];
            c2d += g_colP2[((size_t)b * 8 + s) * WW + tid];
        }
        scol1[tid] = c1; scol2[tid] = c2d;
    }
    const float* im = fr + (size_t)b * NPIX;
    for (int idx = tid; idx < 40 * 512; idx += 512) {
        int r = idx >> 9, c = idx & 511;
        int y = (r < 20) ? r : (472 + r);
        sedge[idx] = im[y * WW + c];
    }
    __syncthreads();

    int wid = tid >> 5, lane = tid & 31;
    for (int r = wid; r < 40; r += 16) {
        double a = 0.0, c2 = 0.0;
        for (int c = lane; c < 512; c += 32) {
            double v = (double)sedge[r * 512 + c];
            a += v; c2 += v * v;
        }
#pragma unroll
        for (int s = 16; s > 0; s >>= 1) {
            a  += __shfl_down_sync(0xffffffffu, a, s);
            c2 += __shfl_down_sync(0xffffffffu, c2, s);
        }
        if (lane == 0) { srow1[r] = a; srow2[r] = c2; }
    }
    for (int idx = tid; idx < 41 * 41; idx += 512) { PP1[idx] = 0.f; PP2[idx] = 0.f; }
    __syncthreads();

    for (int idx = tid; idx < 1600; idx += 512) {
        int r = idx / 40, cc = idx - r * 40;
        int col = (cc < 20) ? cc : (472 + cc);
        float v = sedge[r * 512 + col];
        PP1[(r + 1) * 41 + cc + 1] = v;
        PP2[(r + 1) * 41 + cc + 1] = v * v;
    }
    {
        double a = scol1[tid], c2 = scol2[tid];
#pragma unroll
        for (int s = 16; s > 0; s >>= 1) {
            a  += __shfl_down_sync(0xffffffffu, a, s);
            c2 += __shfl_down_sync(0xffffffffu, c2, s);
        }
        if (lane == 0) { spart1[wid] = a; spart2[wid] = c2; }
    }
    __syncthreads();

    if (tid < 41) {
        float a = 0.f, c2 = 0.f;
        for (int c = 0; c < 41; ++c) {
            a  += PP1[tid * 41 + c]; PP1[tid * 41 + c] = a;
            c2 += PP2[tid * 41 + c]; PP2[tid * 41 + c] = c2;
        }
    }
    if (tid == 64)  { double a = 0; rowPre1[0] = 0; for (int r = 0; r < 40; ++r) { a += srow1[r]; rowPre1[r+1] = a; } }
    if (tid == 96)  { double a = 0; rowPre2[0] = 0; for (int r = 0; r < 40; ++r) { a += srow2[r]; rowPre2[r+1] = a; } }
    if (tid == 128) { double a = 0; colPre1[0] = 0; for (int c = 0; c < 20; ++c) { a += scol1[c]; colPre1[c+1] = a; } }
    if (tid == 160) { double a = 0; colPre2[0] = 0; for (int c = 0; c < 20; ++c) { a += scol2[c]; colPre2[c+1] = a; } }
    if (tid == 192) { double a = 0; colSuf1[20] = 0; for (int j = 19; j >= 0; --j) { a += scol1[492+j]; colSuf1[j] = a; } }
    if (tid == 224) { double a = 0; colSuf2[20] = 0; for (int j = 19; j >= 0; --j) { a += scol2[492+j]; colSuf2[j] = a; } }
    if (tid == 256) { double a = 0; for (int w = 0; w < 16; ++w) a += spart1[w]; sS1s = a; }
    if (tid == 288) { double a = 0; for (int w = 0; w < 16; ++w) a += spart2[w]; sS2s = a; }
    __syncthreads();

    if (tid < 41) {
        float a = 0.f, c2 = 0.f;
        for (int r = 0; r < 41; ++r) {
            a  += PP1[r * 41 + tid]; PP1[r * 41 + tid] = a;
            c2 += PP2[r * 41 + tid]; PP2[r * 41 + tid] = c2;
        }
    }
    __syncthreads();

#define RECT(PP, r0, r1, c0, c1) \
    (PP[(r1)*41+(c1)] - PP[(r0)*41+(c1)] - PP[(r1)*41+(c0)] + PP[(r0)*41+(c0)])
    if (tid < NS) {
        int p = tid / SH, j = tid - p * SH;
        double rsum1 = rowPre1[p] + (rowPre1[40] - rowPre1[p + 20]);
        double rsum2 = rowPre2[p] + (rowPre2[40] - rowPre2[p + 20]);
        double csum1 = colPre1[j] + colSuf1[j];
        double csum2 = colPre2[j] + colSuf2[j];
        float q1 = RECT(PP1, 0, p, 0, j) + RECT(PP1, 0, p, 20 + j, 40)
                 + RECT(PP1, p + 20, 40, 0, j) + RECT(PP1, p + 20, 40, 20 + j, 40);
        float q2 = RECT(PP2, 0, p, 0, j) + RECT(PP2, 0, p, 20 + j, 40)
                 + RECT(PP2, p + 20, 40, 0, j) + RECT(PP2, p + 20, 40, 20 + j, 40);
        double w1 = sS1s - rsum1 - csum1 + (double)q1;
        double w2 = sS2s - rsum2 - csum2 + (double)q2;
        double m1 = w1 / KAREA;
        double m2 = w2 / KAREA;
        double var = m2 - m1 * m1 / KAREA + EPS;
        float vf = (float)var;
        if (vf < 0.f) vf = 0.f;
        sden[tid] = sqrtf(vf);
    }
#undef RECT
    __syncthreads();

    // ---- peak phase ----
    double tsum = 0.0, tsum2 = 0.0;
#pragma unroll
    for (int s = 0; s < 8; ++s) { tsum += g_tpart1[s]; tsum2 += g_tpart2[s]; }
    float stv  = sqrtf((float)(tsum2 - tsum * tsum / (double)NPIX + EPS));
    float cfix = (float)(sS1s * tsum / (double)NPIX);
    if (tid < NS) {
        float ccv = fabsf(g_cc[(size_t)b * NS + tid] - cfix);
        float v = ccv / (stv * sden[tid]);
        if (!(v == v)) v = 0.f;
        sncc[tid] = v;
    }
    __syncthreads();
    rv[tid] = (tid < NS) ? sncc[tid] : -1.f;
    ri[tid] = tid;
    __syncthreads();
    for (int st = 256; st > 0; st >>= 1) {
        if (tid < st) {
            float ov = rv[tid + st]; int oi = ri[tid + st];
            if (ov > rv[tid] || (ov == rv[tid] && oi < ri[tid])) { rv[tid] = ov; ri[tid] = oi; }
        }
        __syncthreads();
    }
    if (tid == 0) {
        int am = ri[0];
        int sx = am / SH, sy = am - sx * SH;
        float shx = -(float)(sx - MS);
        float shy = -(float)(sy - MS);
        int xm = sx - 1; if (xm < 0) xm += SH;
        int xp = sx + 1; if (xp > SH - 1) xp = SH - 1;
        int ym = sy - 1; if (ym < 0) ym += SH;
        int yp = sy + 1; if (yp > SH - 1) yp = SH - 1;
        float lxm = logf(sncc[xm * SH + sy]);
        float lxp = logf(sncc[xp * SH + sy]);
        float lym = logf(sncc[sx * SH + ym]);
        float lyp = logf(sncc[sx * SH + yp]);
        float lc4 = 4.f * logf(sncc[sx * SH + sy]);
        shx -= (lxm - lxp) / (2.f * lxm - lc4 + 2.f * lxp);
        shy -= (lym - lyp) / (2.f * lym - lc4 + 2.f * lyp);
        g_shift[b * 2 + 0] = shx;
        g_shift[b * 2 + 1] = shy;
    }
}

// ---------------- K4: bilinear warp (constant weights) + transposed store ----------------
__global__ void __launch_bounds__(256) k_warp(const float* __restrict__ fr,
                                              float* __restrict__ out) {
    int b = blockIdx.z;
    int X0 = blockIdx.x * 32, Y0 = blockIdx.y * 32;
    float dy = g_shift[b * 2 + 0];
    float dx = g_shift[b * 2 + 1];
    float fy = floorf(-dy), fx = floorf(-dx);
    int Ay = (int)fy, Ax = (int)fx;
    float wy = -dy - fy, wx = -dx - fx;
    float c00 = (1.f - wy) * (1.f - wx);
    float c01 = (1.f - wy) * wx;
    float c10 = wy * (1.f - wx);
    float c11 = wy * wx;

    __shared__ float sp[33 * 37];
    const float* im = fr + (size_t)b * NPIX;
    for (int idx = threadIdx.x; idx < 33 * 33; idx += 256) {
        int r = idx / 33, c = idx - r * 33;
        int gy = Y0 + Ay + r, gx = X0 + Ax + c;
        float v = (gy >= 0 && gy < HH && gx >= 0 && gx < WW) ? im[gy * WW + gx] : 0.f;
        sp[r * 37 + c] = v;
    }
    __syncthreads();

    int tx = threadIdx.x >> 3;
    int qy = (threadIdx.x & 7) << 2;
    float cA[5], cB[5];
#pragma unroll
    for (int i = 0; i < 5; ++i) {
        cA[i] = sp[(qy + i) * 37 + tx];
        cB[i] = sp[(qy + i) * 37 + tx + 1];
    }
    float4 o;
    o.x = fmaf(c00, cA[0], fmaf(c01, cB[0], fmaf(c10, cA[1], c11 * cB[1])));
    o.y = fmaf(c00, cA[1], fmaf(c01, cB[1], fmaf(c10, cA[2], c11 * cB[2])));
    o.z = fmaf(c00, cA[2], fmaf(c01, cB[2], fmaf(c10, cA[3], c11 * cB[3])));
    o.w = fmaf(c00, cA[3], fmaf(c01, cB[3], fmaf(c10, cA[4], c11 * cB[4])));
    *(float4*)(out + (size_t)b * NPIX + (size_t)(X0 + tx) * HH + Y0 + qy) = o;
}

// ---------------- launch ----------------
extern "C" void kernel_launch(void* const* d_in, const int* in_sizes, int n_in,
                              void* d_out, int out_size) {
    const float* fr = (const float*)d_in[0];
    const float* tp = (const float*)d_in[1];
    if (n_in >= 2 && in_sizes[0] < in_sizes[1]) { const float* t = fr; fr = tp; tp = t; }
    float* out = (float*)d_out;

    cudaFuncSetAttribute(k_corr,      cudaFuncAttributeMaxDynamicSharedMemorySize, SMEM_CORR);
    cudaFuncSetAttribute(k_statspeak, cudaFuncAttributeMaxDynamicSharedMemorySize, SMEM_SP);

    k_colpart<<<dim3(NB + 1, 8), 512>>>(fr, tp);
    k_corr<<<dim3(NBAND, 8), CTH, SMEM_CORR>>>(fr, tp);
    k_statspeak<<<NB, 512, SMEM_SP>>>(fr);
    k_warp<<<dim3(16, 16, NB), 256>>>(fr, out);
}

// round 16
// speedup vs baseline: 1.1409x; 1.0762x over previous
#include <cuda_runtime.h>
#include <math.h>

#define HH 512
#define WW 512
#define NB 32
#define MS 10
#define SH 21            // 2*MS+1
#define NS 441           // SH*SH
#define NPIX (HH*WW)     // 262144
#define KAREA (492.0*492.0)
#define EPS 1e-8

#define TBAND 14                 // image rows per band
#define NBAND 37                 // 37*14 = 518 >= 512
#define TROWS 34                 // TBAND + 20
#define TCOLS 532
#define ISTR 516
#define CTH 294                  // 21 p-values x 14 rows
#define SMEM_CORR ((TROWS*TCOLS + TBAND*ISTR) * 4) // 101248
#define SMEM_CP (20*512*4)       // colpart edge staging

// ---------------- scratch ----------------
__device__ double g_tpart1[8], g_tpart2[8];    // per-slab template stats
__device__ double g_colP1[NB*8*WW];            // per-slab column sums
__device__ double g_colP2[NB*8*WW];
__device__ double g_rows1[NB*40], g_rows2[NB*40]; // edge-row sums
__device__ float  g_corner[NB*40*40];          // edge-corner grid values
__device__ float  g_cc[NB*NS];                 // accumulated correlations
__device__ float  g_shift[NB*2];

// ---------------- K1: per-slab column sums + edge rows + template stats ----------------
__global__ void __launch_bounds__(512) k_colpart(const float* __restrict__ fr,
                                                 const float* __restrict__ tp) {
    extern __shared__ float sedge[];   // 20 x 512 (slab 0/7 only)
    int b = blockIdx.x;          // 0..NB ; b==NB -> template slab duty
    int slab = blockIdx.y;       // 0..7
    int x = threadIdx.x;         // 512
    int y0 = slab * 64;
    const float* src = (b < NB) ? (fr + (size_t)b * NPIX) : tp;

    float s1a = 0.f, s1b = 0.f, s2a = 0.f, s2b = 0.f;
#pragma unroll 4
    for (int y = y0; y < y0 + 64; y += 2) {
        float v0 = src[y * WW + x];
        float v1 = src[(y + 1) * WW + x];
        s1a += v0; s1b += v1;
        s2a = fmaf(v0, v0, s2a); s2b = fmaf(v1, v1, s2b);
    }
    double d1 = (double)s1a + (double)s1b;
    double d2 = (double)s2a + (double)s2b;

    if (b < NB) {
        g_colP1[((size_t)b * 8 + slab) * WW + x] = d1;
        g_colP2[((size_t)b * 8 + slab) * WW + x] = d2;
        if (slab == 0 || slab == 7) {
            int rbase = (slab == 0) ? 0 : 20;      // output row block
            int ybase = (slab == 0) ? 0 : 492;     // source rows
            // stage 20 edge rows (cached reads)
            for (int r = 0; r < 20; ++r)
                sedge[r * 512 + x] = src[(ybase + r) * WW + x];
            __syncthreads();
            // per-row fp64 sums (same order as before: warp-strided + shuffle)
            int wid = x >> 5, lane = x & 31;
            for (int r = wid; r < 20; r += 16) {
                double a = 0.0, c2 = 0.0;
                for (int c = lane; c < 512; c += 32) {
                    double v = (double)sedge[r * 512 + c];
                    a += v; c2 += v * v;
                }
#pragma unroll
                for (int s = 16; s > 0; s >>= 1) {
                    a  += __shfl_down_sync(0xffffffffu, a, s);
                    c2 += __shfl_down_sync(0xffffffffu, c2, s);
                }
                if (lane == 0) {
                    g_rows1[b * 40 + rbase + r] = a;
                    g_rows2[b * 40 + rbase + r] = c2;
                }
            }
            // corner grid values
            int c40 = -1;
            if (x < 20) c40 = x;
            else if (x >= 492) c40 = x - 472;      // 492->20 .. 511->39
            if (c40 >= 0) {
                for (int r = 0; r < 20; ++r)
                    g_corner[((size_t)b * 40 + rbase + r) * 40 + c40] = sedge[r * 512 + x];
            }
        }
    } else {
        __shared__ double r1[512], r2[512];
        r1[x] = d1; r2[x] = d2;
        __syncthreads();
        for (int st = 256; st > 0; st >>= 1) {
            if (x < st) { r1[x] += r1[x + st]; r2[x] += r2[x + st]; }
            __syncthreads();
        }
        if (x == 0) { g_tpart1[slab] = r1[0]; g_tpart2[slab] = r2[0]; }
        // zero 1/8 of g_cc
        int base = slab * (NB * NS / 8);
        for (int i = x; i < NB * NS / 8; i += 512) g_cc[base + i] = 0.f;
    }
}

// ---------------- K2: the correlation (hot kernel; R11 verbatim, frozen) ----------------
template<int SLOT>
__device__ __forceinline__ float wslot(const float4* w) {
    return ((SLOT & 3) == 0) ? w[(SLOT >> 2) & 7].x
         : ((SLOT & 3) == 1) ? w[(SLOT >> 2) & 7].y
         : ((SLOT & 3) == 2) ? w[(SLOT >> 2) & 7].z
                             : w[(SLOT >> 2) & 7].w;
}

template<int X, int J> struct FmaJ {
    static __device__ __forceinline__ void run(float v, const float4* w, float* acc) {
        acc[J] = fmaf(v, wslot<(X + 20 - J) & 31>(w), acc[J]);
        FmaJ<X, J + 1>::run(v, w, acc);
    }
};
template<int X> struct FmaJ<X, SH> {
    static __device__ __forceinline__ void run(float, const float4*, float*) {}
};

template<int SG, bool LAST> struct Step {
    static __device__ __forceinline__ void run(const float* __restrict__ tr,
                                               const float* __restrict__ ir,
                                               float4* w, float4* iv, float* acc) {
        iv[(SG + 1) & 1] = *(const float4*)(ir + 4 * SG + 4);   // prefetch next 4 px
        FmaJ<4 * SG + 0, 0>::run(iv[SG & 1].x, w, acc);
        FmaJ<4 * SG + 1, 0>::run(iv[SG & 1].y, w, acc);
        FmaJ<4 * SG + 2, 0>::run(iv[SG & 1].z, w, acc);
        FmaJ<4 * SG + 3, 0>::run(iv[SG & 1].w, w, acc);
        if (!LAST || SG <= 4)
            w[SG] = *(const float4*)(tr + 4 * SG + 32);         // refill dead quad
        Step<SG + 1, LAST>::run(tr, ir, w, iv, acc);
    }
};
template<bool LAST> struct Step<8, LAST> {
    static __device__ __forceinline__ void run(const float*, const float*,
                                               float4*, float4*, float*) {}
};

__global__ void __launch_bounds__(CTH, 2)
k_corr(const float* __restrict__ fr, const float* __restrict__ tp) {
    int band = blockIdx.x;                  // 0..36
    int fg   = blockIdx.y;                  // 0..7 (4 frames each)
    int y0 = band * TBAND;
    extern __shared__ float sm[];
    float* sm_t = sm;                       // TROWS x TCOLS
    float* sm_i = sm + TROWS * TCOLS;       // TBAND x ISTR
    int tid = threadIdx.x;

    // template tile once per block (shared by 4 frames); wrapped rows/cols
    for (int idx = tid; idx < TROWS * 256; idx += CTH) {
        int r = idx >> 8, c2 = idx & 255;
        int gy = (y0 - MS + r) & (HH - 1);
        float2 v = *(const float2*)(tp + gy * WW + 2 * c2);
        *(float2*)(sm_t + r * TCOLS + 10 + 2 * c2) = v;
    }
    for (int idx = tid; idx < TROWS * 20; idx += CTH) {
        int r = idx / 20, e = idx - r * 20;
        int c = (e < 10) ? e : (e + 512);
        int gy = (y0 - MS + r) & (HH - 1);
        int gx = (c - 10) & (WW - 1);
        sm_t[r * TCOLS + c] = tp[gy * WW + gx];
    }

    int yl = tid % TBAND;                   // image row in band
    int p  = tid / TBAND;                   // shift-row index 0..20
    const float* trow0 = sm_t + (yl + 2 * MS - p) * TCOLS;
    const float* irow0 = sm_i + yl * ISTR;

    for (int f = 0; f < 4; ++f) {
        int b = fg * 4 + f;
        const float* im = fr + (size_t)b * NPIX + (size_t)y0 * WW;
        __syncthreads();                    // sred of prev frame fully consumed
        for (int idx = tid; idx < TBAND * 128; idx += CTH) {
            int r = idx >> 7, c4 = idx & 127;
            float4 v;
            if (y0 + r < HH) v = *(const float4*)(im + r * WW + 4 * c4);
            else             v = make_float4(0.f, 0.f, 0.f, 0.f);
            *(float4*)(sm_i + r * ISTR + 4 * c4) = v;
        }
        __syncthreads();

        float acc[SH];
#pragma unroll
        for (int j = 0; j < SH; ++j) acc[j] = 0.f;
        float4 w[8];
#pragma unroll
        for (int m = 0; m < 8; ++m) w[m] = *(const float4*)(trow0 + 4 * m);
        float4 iv[2];
        iv[0] = *(const float4*)irow0;

        const float* tr = trow0;
        const float* ir = irow0;
#pragma unroll 1
        for (int it = 0; it < 15; ++it) {
            Step<0, false>::run(tr, ir, w, iv, acc);
            tr += 32; ir += 32;
        }
        Step<0, true>::run(tr, ir, w, iv, acc);

        __syncthreads();                    // all reads of sm_i done
        float* sred = sm_i;                 // reuse image buffer: 441*14 floats
#pragma unroll
        for (int j = 0; j < SH; ++j) sred[(p * SH + j) * TBAND + yl] = acc[j];
        __syncthreads();
        for (int s = tid; s < NS; s += CTH) {
            float v = 0.f;
#pragma unroll
            for (int k = 0; k < TBAND; ++k) v += sred[s * TBAND + k];
            atomicAdd(&g_cc[(size_t)b * NS + s], v);
        }
    }
}

// ---------------- K3: denominators + ncc + argmax + subpixel (lean) ----------------
__global__ void __launch_bounds__(512) k_statspeak() {
    __shared__ double scol1[512], scol2[512];
    __shared__ double srow1[40], srow2[40];
    __shared__ double rowPre1[41], rowPre2[41];
    __shared__ double colPre1[21], colPre2[21];
    __shared__ double colSuf1[21], colSuf2[21];
    __shared__ double spart1[16], spart2[16];
    __shared__ double sS1s, sS2s;
    __shared__ float PP1[41*41], PP2[41*41];
    __shared__ float sden[NS];
    __shared__ float sncc[NS];
    __shared__ float rv[512];
    __shared__ int   ri[512];

    int b = blockIdx.x, tid = threadIdx.x;   // 512 threads
    {
        double c1 = 0.0, c2d = 0.0;
#pragma unroll
        for (int s = 0; s < 8; ++s) {
            c1  += g_colP1[((size_t)b * 8 + s) * WW + tid];
            c2d += g_colP2[((size_t)b * 8 + s) * WW + tid];
        }
        scol1[tid] = c1; scol2[tid] = c2d;
    }
    if (tid < 40) {
        srow1[tid] = g_rows1[b * 40 + tid];
        srow2[tid] = g_rows2[b * 40 + tid];
    }
    for (int idx = tid; idx < 41 * 41; idx += 512) { PP1[idx] = 0.f; PP2[idx] = 0.f; }
    __syncthreads();

    // fill PP interior from precomputed corner grid
    for (int idx = tid; idx < 1600; idx += 512) {
        int r = idx / 40, cc = idx - r * 40;
        float v = g_corner[(size_t)b * 1600 + idx];
        PP1[(r + 1) * 41 + cc + 1] = v;
        PP2[(r + 1) * 41 + cc + 1] = v * v;
    }
    {
        int wid = tid >> 5, lane = tid & 31;
        double a = scol1[tid], c2 = scol2[tid];
#pragma unroll
        for (int s = 16; s > 0; s >>= 1) {
            a  += __shfl_down_sync(0xffffffffu, a, s);
            c2 += __shfl_down_sync(0xffffffffu, c2, s);
        }
        if (lane == 0) { spart1[wid] = a; spart2[wid] = c2; }
    }
    __syncthreads();

    if (tid < 41) {
        float a = 0.f, c2 = 0.f;
        for (int c = 0; c < 41; ++c) {
            a  += PP1[tid * 41 + c]; PP1[tid * 41 + c] = a;
            c2 += PP2[tid * 41 + c]; PP2[tid * 41 + c] = c2;
        }
    }
    if (tid == 64)  { double a = 0; rowPre1[0] = 0; for (int r = 0; r < 40; ++r) { a += srow1[r]; rowPre1[r+1] = a; } }
    if (tid == 96)  { double a = 0; rowPre2[0] = 0; for (int r = 0; r < 40; ++r) { a += srow2[r]; rowPre2[r+1] = a; } }
    if (tid == 128) { double a = 0; colPre1[0] = 0; for (int c = 0; c < 20; ++c) { a += scol1[c]; colPre1[c+1] = a; } }
    if (tid == 160) { double a = 0; colPre2[0] = 0; for (int c = 0; c < 20; ++c) { a += scol2[c]; colPre2[c+1] = a; } }
    if (tid == 192) { double a = 0; colSuf1[20] = 0; for (int j = 19; j >= 0; --j) { a += scol1[492+j]; colSuf1[j] = a; } }
    if (tid == 224) { double a = 0; colSuf2[20] = 0; for (int j = 19; j >= 0; --j) { a += scol2[492+j]; colSuf2[j] = a; } }
    if (tid == 256) { double a = 0; for (int w = 0; w < 16; ++w) a += spart1[w]; sS1s = a; }
    if (tid == 288) { double a = 0; for (int w = 0; w < 16; ++w) a += spart2[w]; sS2s = a; }
    __syncthreads();

    if (tid < 41) {
        float a = 0.f, c2 = 0.f;
        for (int r = 0; r < 41; ++r) {
            a  += PP1[r * 41 + tid]; PP1[r * 41 + tid] = a;
            c2 += PP2[r * 41 + tid]; PP2[r * 41 + tid] = c2;
        }
    }
    __syncthreads();

#define RECT(PP, r0, r1, c0, c1) \
    (PP[(r1)*41+(c1)] - PP[(r0)*41+(c1)] - PP[(r1)*41+(c0)] + PP[(r0)*41+(c0)])
    if (tid < NS) {
        int p = tid / SH, j = tid - p * SH;
        double rsum1 = rowPre1[p] + (rowPre1[40] - rowPre1[p + 20]);
        double rsum2 = rowPre2[p] + (rowPre2[40] - rowPre2[p + 20]);
        double csum1 = colPre1[j] + colSuf1[j];
        double csum2 = colPre2[j] + colSuf2[j];
        float q1 = RECT(PP1, 0, p, 0, j) + RECT(PP1, 0, p, 20 + j, 40)
                 + RECT(PP1, p + 20, 40, 0, j) + RECT(PP1, p + 20, 40, 20 + j, 40);
        float q2 = RECT(PP2, 0, p, 0, j) + RECT(PP2, 0, p, 20 + j, 40)
                 + RECT(PP2, p + 20, 40, 0, j) + RECT(PP2, p + 20, 40, 20 + j, 40);
        double w1 = sS1s - rsum1 - csum1 + (double)q1;
        double w2 = sS2s - rsum2 - csum2 + (double)q2;
        double m1 = w1 / KAREA;
        double m2 = w2 / KAREA;
        double var = m2 - m1 * m1 / KAREA + EPS;
        float vf = (float)var;
        if (vf < 0.f) vf = 0.f;
        sden[tid] = sqrtf(vf);
    }
#undef RECT
    __syncthreads();

    // ---- peak phase ----
    double tsum = 0.0, tsum2 = 0.0;
#pragma unroll
    for (int s = 0; s < 8; ++s) { tsum += g_tpart1[s]; tsum2 += g_tpart2[s]; }
    float stv  = sqrtf((float)(tsum2 - tsum * tsum / (double)NPIX + EPS));
    float cfix = (float)(sS1s * tsum / (double)NPIX);
    if (tid < NS) {
        float ccv = fabsf(g_cc[(size_t)b * NS + tid] - cfix);
        float v = ccv / (stv * sden[tid]);
        if (!(v == v)) v = 0.f;
        sncc[tid] = v;
    }
    __syncthreads();
    rv[tid] = (tid < NS) ? sncc[tid] : -1.f;
    ri[tid] = tid;
    __syncthreads();
    for (int st = 256; st > 0; st >>= 1) {
        if (tid < st) {
            float ov = rv[tid + st]; int oi = ri[tid + st];
            if (ov > rv[tid] || (ov == rv[tid] && oi < ri[tid])) { rv[tid] = ov; ri[tid] = oi; }
        }
        __syncthreads();
    }
    if (tid == 0) {
        int am = ri[0];
        int sx = am / SH, sy = am - sx * SH;
        float shx = -(float)(sx - MS);
        float shy = -(float)(sy - MS);
        int xm = sx - 1; if (xm < 0) xm += SH;
        int xp = sx + 1; if (xp > SH - 1) xp = SH - 1;
        int ym = sy - 1; if (ym < 0) ym += SH;
        int yp = sy + 1; if (yp > SH - 1) yp = SH - 1;
        float lxm = logf(sncc[xm * SH + sy]);
        float lxp = logf(sncc[xp * SH + sy]);
        float lym = logf(sncc[sx * SH + ym]);
        float lyp = logf(sncc[sx * SH + yp]);
        float lc4 = 4.f * logf(sncc[sx * SH + sy]);
        shx -= (lxm - lxp) / (2.f * lxm - lc4 + 2.f * lxp);
        shy -= (lym - lyp) / (2.f * lym - lc4 + 2.f * lyp);
        g_shift[b * 2 + 0] = shx;
        g_shift[b * 2 + 1] = shy;
    }
}

// ---------------- K4: bilinear warp (constant weights) + transposed store ----------------
__global__ void __launch_bounds__(256) k_warp(const float* __restrict__ fr,
                                              float* __restrict__ out) {
    int b = blockIdx.z;
    int X0 = blockIdx.x * 32, Y0 = blockIdx.y * 32;
    float dy = g_shift[b * 2 + 0];
    float dx = g_shift[b * 2 + 1];
    float fy = floorf(-dy), fx = floorf(-dx);
    int Ay = (int)fy, Ax = (int)fx;
    float wy = -dy - fy, wx = -dx - fx;
    float c00 = (1.f - wy) * (1.f - wx);
    float c01 = (1.f - wy) * wx;
    float c10 = wy * (1.f - wx);
    float c11 = wy * wx;

    __shared__ float sp[33 * 37];
    const float* im = fr + (size_t)b * NPIX;
    for (int idx = threadIdx.x; idx < 33 * 33; idx += 256) {
        int r = idx / 33, c = idx - r * 33;
        int gy = Y0 + Ay + r, gx = X0 + Ax + c;
        float v = (gy >= 0 && gy < HH && gx >= 0 && gx < WW) ? im[gy * WW + gx] : 0.f;
        sp[r * 37 + c] = v;
    }
    __syncthreads();

    int tx = threadIdx.x >> 3;
    int qy = (threadIdx.x & 7) << 2;
    float cA[5], cB[5];
#pragma unroll
    for (int i = 0; i < 5; ++i) {
        cA[i] = sp[(qy + i) * 37 + tx];
        cB[i] = sp[(qy + i) * 37 + tx + 1];
    }
    float4 o;
    o.x = fmaf(c00, cA[0], fmaf(c01, cB[0], fmaf(c10, cA[1], c11 * cB[1])));
    o.y = fmaf(c00, cA[1], fmaf(c01, cB[1], fmaf(c10, cA[2], c11 * cB[2])));
    o.z = fmaf(c00, cA[2], fmaf(c01, cB[2], fmaf(c10, cA[3], c11 * cB[3])));
    o.w = fmaf(c00, cA[3], fmaf(c01, cB[3], fmaf(c10, cA[4], c11 * cB[4])));
    *(float4*)(out + (size_t)b * NPIX + (size_t)(X0 + tx) * HH + Y0 + qy) = o;
}

// ---------------- launch ----------------
extern "C" void kernel_launch(void* const* d_in, const int* in_sizes, int n_in,
                              void* d_out, int out_size) {
    const float* fr = (const float*)d_in[0];
    const float* tp = (const float*)d_in[1];
    if (n_in >= 2 && in_sizes[0] < in_sizes[1]) { const float* t = fr; fr = tp; tp = t; }
    float* out = (float*)d_out;

    cudaFuncSetAttribute(k_corr,    cudaFuncAttributeMaxDynamicSharedMemorySize, SMEM_CORR);
    cudaFuncSetAttribute(k_colpart, cudaFuncAttributeMaxDynamicSharedMemorySize, SMEM_CP);

    k_colpart<<<dim3(NB + 1, 8), 512, SMEM_CP>>>(fr, tp);
    k_corr<<<dim3(NBAND, 8), CTH, SMEM_CORR>>>(fr, tp);
    k_statspeak<<<NB, 512>>>();
    k_warp<<<dim3(16, 16, NB), 256>>>(fr, out);
}